// round 6
// baseline (speedup 1.0000x reference)
#include <cuda_runtime.h>
#include <cuda_fp16.h>
#include <math.h>
#include <stdint.h>

#define B_ROWS 262144
#define HID 512
#define NB1 512
#define NPART 2048         // GEMM bm count = stats partials

// ---------------- device scratch ----------------
__device__ __half g_B[HID * HID];                 // [n][k] = w2[k][n] fp16
__device__ __half g_h2h[(size_t)B_ROWS * HID];    // h2 fp16 (256 MB)
__device__ float  g_feat[B_ROWS * 4];
__device__ double g_p1[NB1 * 14];
__device__ float  g_W1eff[4 * HID];
__device__ float  g_shift1[HID];                  // folded: beta1 - meanX @ W1eff
__device__ float  g_p2s[(size_t)NPART * HID];
__device__ float  g_p2q[(size_t)NPART * HID];
__device__ float  g_a2[HID];
__device__ float  g_d2[HID];

// ---------------- PTX helpers (sm_80-level, safe at compute_103) ----------------
__device__ __forceinline__ uint32_t smem_u32(const void* p) {
    uint32_t a;
    asm("{ .reg .u64 t; cvta.to.shared.u64 t, %1; cvt.u32.u64 %0, t; }" : "=r"(a) : "l"(p));
    return a;
}
#define CP_ASYNC16(dst, src) \
    asm volatile("cp.async.cg.shared.global [%0], [%1], 16;" :: "r"(dst), "l"(src) : "memory")
#define CP_COMMIT() asm volatile("cp.async.commit_group;" ::: "memory")
#define CP_WAIT(n)  asm volatile("cp.async.wait_group %0;" :: "n"(n) : "memory")
#define LDSM_X4(r0, r1, r2, r3, addr) \
    asm volatile("ldmatrix.sync.aligned.m8n8.x4.shared.b16 {%0,%1,%2,%3}, [%4];" \
        : "=r"(r0), "=r"(r1), "=r"(r2), "=r"(r3) : "r"(addr))
#define MMA16816F16(d, a, b0, b1) \
    asm volatile("mma.sync.aligned.m16n8k16.row.col.f32.f16.f16.f32 " \
        "{%0,%1,%2,%3},{%4,%5,%6,%7},{%8,%9},{%0,%1,%2,%3};" \
        : "+f"((d)[0]), "+f"((d)[1]), "+f"((d)[2]), "+f"((d)[3]) \
        : "r"((a)[0]), "r"((a)[1]), "r"((a)[2]), "r"((a)[3]), "r"(b0), "r"(b1))

__device__ __forceinline__ float ftanh(float x) {        // accurate path (k6)
    x = fminf(fmaxf(x, -9.0f), 9.0f);
    float e = __expf(2.0f * x);
    return __fdividef(e - 1.0f, e + 1.0f);
}
__device__ __forceinline__ float htanh(float x) {        // HW approx (pre-fp16 rounding)
    float y;
    asm("tanh.approx.f32 %0, %1;" : "=f"(y) : "f"(x));
    return y;
}

// ---------------- K1: features + (sum, second-moment) partials ----------------
__global__ void k1_feat(const float* __restrict__ x,
                        const float* __restrict__ tset,
                        const float* __restrict__ tenv,
                        const float* __restrict__ ctab)
{
    __shared__ float sxs[9], sys[14], stab[9 * 14];
    int tid = threadIdx.x;
    if (tid < 9)   sxs[tid] = tset[tid];
    if (tid < 14)  sys[tid] = tenv[tid];
    if (tid < 126) stab[tid] = ctab[tid];
    __syncthreads();

    double s0 = 0, s1 = 0, s2 = 0, s3 = 0;
    double m00 = 0, m01 = 0, m02 = 0, m03 = 0, m11 = 0, m12 = 0, m13 = 0,
           m22 = 0, m23 = 0, m33 = 0;

    for (int r = blockIdx.x * blockDim.x + tid; r < B_ROWS; r += gridDim.x * blockDim.x) {
        const float* xr = x + (size_t)r * 15;
        float amb = xr[1], fl = xr[2], fr = xr[3];
        float incar = xr[8], breq = xr[9], cin = xr[10];

        float yq = fminf(fmaxf(amb, sys[0]), sys[13]);
        int j = 0;
        #pragma unroll
        for (int k = 1; k <= 12; k++) j += (sys[k] <= yq);
        float y0 = sys[j], y1 = sys[j + 1];
        float ty = (yq - y0) / (y1 - y0);

        auto interp = [&](float xq) -> float {
            xq = fminf(fmaxf(xq, sxs[0]), sxs[8]);
            int i = 0;
            #pragma unroll
            for (int k = 1; k <= 7; k++) i += (sxs[k] <= xq);
            float x0 = sxs[i], x1 = sxs[i + 1];
            float tx = (xq - x0) / (x1 - x0);
            float f00 = stab[i * 14 + j],       f01 = stab[i * 14 + j + 1];
            float f10 = stab[(i + 1) * 14 + j], f11 = stab[(i + 1) * 14 + j + 1];
            return f00 * (1.f - tx) * (1.f - ty) + f10 * tx * (1.f - ty)
                 + f01 * (1.f - tx) * ty        + f11 * tx * ty;
        };

        float f0 = interp(fl) - incar;
        float f1 = interp(fr) - incar;
        float f2 = amb;
        float f3 = breq - cin;
        *(float4*)&g_feat[(size_t)r * 4] = make_float4(f0, f1, f2, f3);

        s0 += f0; s1 += f1; s2 += f2; s3 += f3;
        m00 += (double)f0 * f0; m01 += (double)f0 * f1; m02 += (double)f0 * f2; m03 += (double)f0 * f3;
        m11 += (double)f1 * f1; m12 += (double)f1 * f2; m13 += (double)f1 * f3;
        m22 += (double)f2 * f2; m23 += (double)f2 * f3; m33 += (double)f3 * f3;
    }

    __shared__ double red[256];
    double vals[14] = {s0, s1, s2, s3, m00, m01, m02, m03, m11, m12, m13, m22, m23, m33};
    for (int q = 0; q < 14; q++) {
        red[tid] = vals[q];
        __syncthreads();
        for (int off = 128; off > 0; off >>= 1) {
            if (tid < off) red[tid] += red[tid + off];
            __syncthreads();
        }
        if (tid == 0) g_p1[blockIdx.x * 14 + q] = red[0];
        __syncthreads();
    }
}

// ---------------- K2: finalize layer-1 BN fold (mean folded into shift) ----------------
__global__ void k2_fin1(const float* __restrict__ w1,
                        const float* __restrict__ g1,
                        const float* __restrict__ beta1)
{
    __shared__ double acc[14];
    __shared__ float C[4][4];
    __shared__ float sMean[4];
    int tid = threadIdx.x;
    if (tid < 14) {
        double s = 0;
        for (int p = 0; p < NB1; p++) s += g_p1[p * 14 + tid];
        acc[tid] = s;
    }
    __syncthreads();
    if (tid == 0) {
        double inv = 1.0 / (double)B_ROWS;
        double mm[4];
        for (int a = 0; a < 4; a++) { mm[a] = acc[a] * inv; sMean[a] = (float)mm[a]; }
        double M[4][4];
        int idx = 4;
        for (int a = 0; a < 4; a++)
            for (int b = a; b < 4; b++) M[a][b] = acc[idx++] * inv;
        for (int a = 0; a < 4; a++)
            for (int b = a; b < 4; b++) {
                double c = M[a][b] - mm[a] * mm[b];
                C[a][b] = (float)c; C[b][a] = (float)c;
            }
    }
    __syncthreads();
    if (tid < HID) {
        float w[4];
        for (int a = 0; a < 4; a++) w[a] = w1[a * HID + tid];
        float var = 0.f;
        for (int a = 0; a < 4; a++)
            for (int b = 0; b < 4; b++) var += w[a] * C[a][b] * w[b];
        float s = g1[tid] * rsqrtf(var + 1e-5f);
        float we[4];
        for (int a = 0; a < 4; a++) { we[a] = w[a] * s; g_W1eff[a * HID + tid] = we[a]; }
        g_shift1[tid] = beta1[tid]
                      - (sMean[0] * we[0] + sMean[1] * we[1] + sMean[2] * we[2] + sMean[3] * we[3]);
    }
}

// ---------------- K2b: transpose w2 -> B [n][k] fp16 ----------------
__global__ void k2b_bsplit(const float* __restrict__ w2)
{
    int idx = blockIdx.x * 256 + threadIdx.x;
    int n = idx >> 9, k = idx & 511;
    g_B[n * HID + k] = __float2half_rn(w2[k * HID + n]);
}

// ---------------- K3b: fused t1-generation + h2 = t1 @ w2 + column stats ----------------
// CTA tile 128x128, 8 warps (warp tile 32x64), KSTAGE=64.
// A slices COMPUTED into smem (tanh of layer-1), B via 3-deep cp.async ring.
#define ROWPAD 144                     // 128B data + 16B pad (conflict-free ldmatrix)
#define ASTAGE_B 18432                 // 128 * ROWPAD
#define BSTAGE_B 18432
#define OFF_BA 0                       // 2 A buffers
#define OFF_BB (2 * ASTAGE_B)          // 36864, 3 B buffers
#define OFF_FEAT (OFF_BB + 3 * BSTAGE_B)   // 92160 (2048 B)
#define OFF_W (OFF_FEAT + 2048)        // 94208: W1eff 4x512 f32 + shift 512 f32
#define GEMM_SMEM (OFF_W + 10240)      // 104448
#define RSTRIDE 136                    // epilogue staging row stride in halves (272B)
#define SST_OFF 36864                  // stats scratch (reuses B region post-loop)

__device__ __forceinline__ void compute_A_stage(char* smem, int s, int ab, int tid)
{
    const int rg = tid >> 3;          // 0..31 -> rows rg*4..+3
    const int cg = tid & 7;           // 0..7  -> k cols cg*8..+7
    const int k0 = s * 64 + cg * 8;
    const float* sW = (const float*)(smem + OFF_W);
    const float4* sfeat = (const float4*)(smem + OFF_FEAT);
    char* abuf = smem + OFF_BA + ab * ASTAGE_B + cg * 16;

    float4 f[4];
    #pragma unroll
    for (int i = 0; i < 4; i++) f[i] = sfeat[rg * 4 + i];

    uint32_t hp[4][4];
    float prev[4];
    #pragma unroll
    for (int j = 0; j < 8; j++) {
        float w0 = sW[0 * 512 + k0 + j];
        float w1 = sW[1 * 512 + k0 + j];
        float w2 = sW[2 * 512 + k0 + j];
        float w3 = sW[3 * 512 + k0 + j];
        float sh = sW[4 * 512 + k0 + j];
        #pragma unroll
        for (int i = 0; i < 4; i++) {
            float v = f[i].x * w0 + f[i].y * w1 + f[i].z * w2 + f[i].w * w3 + sh;
            float h = htanh(v);
            if (j & 1) {
                __half2 p = __floats2half2_rn(prev[i], h);
                hp[i][j >> 1] = *(uint32_t*)&p;
            } else {
                prev[i] = h;
            }
        }
    }
    #pragma unroll
    for (int i = 0; i < 4; i++)
        *(uint4*)(abuf + (rg * 4 + i) * ROWPAD) = *(uint4*)&hp[i][0];
}

__global__ void __launch_bounds__(256, 2) k3b_gemm()
{
    extern __shared__ char smem[];
    const uint32_t sb = smem_u32(smem);
    const int tid = threadIdx.x;
    const int wid = tid >> 5, lane = tid & 31;
    const int bn = blockIdx.x, bm = blockIdx.y;
    const size_t arow0 = (size_t)bm * 128;
    const int ncol0 = bn * 128;

    // ---- prologue: group0 = {feat, W1eff, shift}; then B0, B1 ----
    if (tid < 128)
        CP_ASYNC16(sb + OFF_FEAT + tid * 16, g_feat + arow0 * 4 + tid * 4);
    for (int c = tid; c < 512; c += 256)
        CP_ASYNC16(sb + OFF_W + c * 16, (const float*)g_W1eff + c * 4);
    if (tid < 128)
        CP_ASYNC16(sb + OFF_W + 8192 + tid * 16, g_shift1 + tid * 4);
    CP_COMMIT();
    #pragma unroll
    for (int st = 0; st < 2; st++) {
        int kk = st * 64;
        #pragma unroll
        for (int h = 0; h < 4; h++) {
            int idx = tid + h * 256;
            int r = idx >> 3, c = idx & 7;
            CP_ASYNC16(sb + OFF_BB + st * BSTAGE_B + (uint32_t)r * ROWPAD + c * 16,
                       g_B + (size_t)(ncol0 + r) * HID + kk + c * 8);
        }
        CP_COMMIT();
    }
    CP_WAIT(2);                 // feat + W ready (B0, B1 may be in flight)
    __syncthreads();
    compute_A_stage(smem, 0, 0, tid);

    const int warp_m = wid & 3;
    const int warp_n = wid >> 2;

    float acc[2][8][4];
    #pragma unroll
    for (int i = 0; i < 2; i++)
        #pragma unroll
        for (int j = 0; j < 8; j++)
            #pragma unroll
            for (int q = 0; q < 4; q++) acc[i][j][q] = 0.f;

    const int a_row = warp_m * 32 + (lane & 15);
    const uint32_t a_koff = (lane >> 4) * 16;
    const int b_row = warp_n * 64 + (lane & 7) + ((lane >> 4) & 1) * 8;
    const uint32_t b_koff = ((lane >> 3) & 1) * 16;

    for (int s = 0; s < 8; s++) {
        if (s < 7) { CP_WAIT(1); } else { CP_WAIT(0); }   // B(s) ready
        __syncthreads();                                  // publishes A(s) + B(s)

        if (s + 2 < 8) {                                  // prefetch B(s+2)
            int kk = (s + 2) * 64;
            int bufb = (s + 2) % 3;
            #pragma unroll
            for (int h = 0; h < 4; h++) {
                int idx = tid + h * 256;
                int r = idx >> 3, c = idx & 7;
                CP_ASYNC16(sb + OFF_BB + bufb * BSTAGE_B + (uint32_t)r * ROWPAD + c * 16,
                           g_B + (size_t)(ncol0 + r) * HID + kk + c * 8);
            }
            CP_COMMIT();
        }

        uint32_t astg = sb + OFF_BA + (s & 1) * ASTAGE_B;
        uint32_t bstg = sb + OFF_BB + (s % 3) * BSTAGE_B;
        #pragma unroll
        for (int ks = 0; ks < 4; ks++) {
            uint32_t kb = ks * 32;
            uint32_t ah[2][4];
            #pragma unroll
            for (int im = 0; im < 2; im++) {
                uint32_t aaddr = astg + (uint32_t)(a_row + im * 16) * ROWPAD + kb + a_koff;
                LDSM_X4(ah[im][0], ah[im][1], ah[im][2], ah[im][3], aaddr);
            }
            #pragma unroll
            for (int ng = 0; ng < 4; ng++) {
                uint32_t baddr = bstg + (uint32_t)(b_row + ng * 16) * ROWPAD + kb + b_koff;
                uint32_t bh[4];
                LDSM_X4(bh[0], bh[1], bh[2], bh[3], baddr);
                #pragma unroll
                for (int im = 0; im < 2; im++) {
                    MMA16816F16(acc[im][ng * 2 + 0], ah[im], bh[0], bh[1]);
                    MMA16816F16(acc[im][ng * 2 + 1], ah[im], bh[2], bh[3]);
                }
            }
        }

        if (s < 7) compute_A_stage(smem, s + 1, (s + 1) & 1, tid);  // overlaps tensor drain
    }
    __syncthreads();   // all ldmatrix/HMMA consumed; smem reusable

    // ---- epilogue 1: pack fp16 into smem staging (conflict-free) ----
    __half* hst = (__half*)smem;          // 128 rows x RSTRIDE halves
    #pragma unroll
    for (int im = 0; im < 2; im++) {
        #pragma unroll
        for (int half = 0; half < 2; half++) {
            int row = warp_m * 32 + im * 16 + (lane >> 2) + half * 8;
            int colb = warp_n * 64 + (lane & 3) * 2;
            #pragma unroll
            for (int ng2 = 0; ng2 < 8; ng2++) {
                __half2 hv = __floats2half2_rn(acc[im][ng2][2 * half], acc[im][ng2][2 * half + 1]);
                *(__half2*)&hst[row * RSTRIDE + colb + ng2 * 8] = hv;
            }
        }
    }

    // ---- epilogue 2: fused column sum/sumsq partials ----
    float* sst = (float*)(smem + SST_OFF);        // [4 warp_m][128 col][2]
    #pragma unroll
    for (int ng2 = 0; ng2 < 8; ng2++) {
        #pragma unroll
        for (int e = 0; e < 2; e++) {
            float s = 0.f, q = 0.f;
            #pragma unroll
            for (int im = 0; im < 2; im++) {
                #pragma unroll
                for (int half = 0; half < 2; half++) {
                    float v = acc[im][ng2][2 * half + e];
                    s += v; q += v * v;
                }
            }
            #pragma unroll
            for (int off = 4; off < 32; off <<= 1) {
                s += __shfl_xor_sync(0xffffffffu, s, off);
                q += __shfl_xor_sync(0xffffffffu, q, off);
            }
            if (lane < 4) {
                int col = warp_n * 64 + ng2 * 8 + lane * 2 + e;
                sst[(warp_m * 128 + col) * 2 + 0] = s;
                sst[(warp_m * 128 + col) * 2 + 1] = q;
            }
        }
    }
    __syncthreads();

    // ---- epilogue 3: coalesced fp16 stores from staging ----
    #pragma unroll
    for (int it = 0; it < 8; it++) {
        int g = it * 256 + tid;               // 2048 chunks of 16B
        int row = g >> 4, ch = g & 15;
        uint4 v = *(uint4*)&hst[row * RSTRIDE + ch * 8];
        *(uint4*)(g_h2h + (arow0 + row) * HID + ncol0 + ch * 8) = v;
    }

    // ---- epilogue 4: reduce stats across warp_m, write partials ----
    if (tid < 256) {
        int col = tid >> 1, sq = tid & 1;
        float v = sst[(0 * 128 + col) * 2 + sq] + sst[(1 * 128 + col) * 2 + sq]
                + sst[(2 * 128 + col) * 2 + sq] + sst[(3 * 128 + col) * 2 + sq];
        size_t gidx = (size_t)bm * HID + bn * 128 + col;
        if (sq == 0) g_p2s[gidx] = v; else g_p2q[gidx] = v;
    }
}

// ---------------- K5: finalize layer-2 BN fold (one block per column) ----------------
__global__ void k5_fin2(const float* __restrict__ g2, const float* __restrict__ beta2)
{
    int c = blockIdx.x;
    int t = threadIdx.x;
    double s = 0, q = 0;
    for (int p = t; p < NPART; p += 256) {
        s += (double)g_p2s[(size_t)p * HID + c];
        q += (double)g_p2q[(size_t)p * HID + c];
    }
    __shared__ double rs[256], rq[256];
    rs[t] = s; rq[t] = q;
    __syncthreads();
    for (int off = 128; off > 0; off >>= 1) {
        if (t < off) { rs[t] += rs[t + off]; rq[t] += rq[t + off]; }
        __syncthreads();
    }
    if (t == 0) {
        double mu  = rs[0] / (double)B_ROWS;
        double var = rq[0] / (double)B_ROWS - mu * mu;
        float a = g2[c] * rsqrtf((float)var + 1e-5f);
        g_a2[c] = a;
        g_d2[c] = beta2[c] - (float)mu * a;
    }
}

// ---------------- K6: out = tanh(a2*h2 + d2) @ w3 + b3 (register-resident consts) ----------------
__global__ void __launch_bounds__(256) k6_out(const float* __restrict__ w3,
                                              const float* __restrict__ b3,
                                              float* __restrict__ out)
{
    int t = threadIdx.x;
    int warp = t >> 5, lane = t & 31;
    float bias = b3[0];

    float ra[16], rd[16], rw[16];
    #pragma unroll
    for (int p = 0; p < 2; p++) {
        int c0 = p * 256 + lane * 8;
        #pragma unroll
        for (int u = 0; u < 8; u++) {
            ra[p * 8 + u] = g_a2[c0 + u];
            rd[p * 8 + u] = g_d2[c0 + u];
            rw[p * 8 + u] = w3[c0 + u];
        }
    }

    int gw = blockIdx.x * 8 + warp;
    int stride = gridDim.x * 8;
    for (int r = gw; r < B_ROWS; r += stride) {
        const __half* row = g_h2h + (size_t)r * HID;
        float acc = 0.f;
        #pragma unroll
        for (int p = 0; p < 2; p++) {
            int c0 = p * 256 + lane * 8;
            uint4 v = *(const uint4*)(row + c0);
            float2 f0 = __half22float2(*(__half2*)&v.x);
            float2 f1 = __half22float2(*(__half2*)&v.y);
            float2 f2 = __half22float2(*(__half2*)&v.z);
            float2 f3 = __half22float2(*(__half2*)&v.w);
            float hv[8] = {f0.x, f0.y, f1.x, f1.y, f2.x, f2.y, f3.x, f3.y};
            #pragma unroll
            for (int u = 0; u < 8; u++) {
                int q = p * 8 + u;
                acc += ftanh(fmaf(ra[q], hv[u], rd[q])) * rw[q];
            }
        }
        #pragma unroll
        for (int off = 16; off; off >>= 1) acc += __shfl_xor_sync(0xffffffffu, acc, off);
        if (lane == 0) out[r] = acc + bias;
    }
}

// ---------------- launch ----------------
extern "C" void kernel_launch(void* const* d_in, const int* in_sizes, int n_in,
                              void* d_out, int out_size)
{
    const float* x     = (const float*)d_in[0];
    const float* tset  = (const float*)d_in[1];
    const float* tenv  = (const float*)d_in[2];
    const float* ctab  = (const float*)d_in[3];
    const float* w1    = (const float*)d_in[4];
    const float* g1    = (const float*)d_in[6];
    const float* beta1 = (const float*)d_in[7];
    const float* w2    = (const float*)d_in[8];
    const float* g2    = (const float*)d_in[10];
    const float* beta2 = (const float*)d_in[11];
    const float* w3    = (const float*)d_in[12];
    const float* b3    = (const float*)d_in[13];
    float* out = (float*)d_out;

    static bool attr_set = false;
    if (!attr_set) {
        cudaFuncSetAttribute(k3b_gemm, cudaFuncAttributeMaxDynamicSharedMemorySize, GEMM_SMEM);
        attr_set = true;
    }

    k1_feat<<<NB1, 256>>>(x, tset, tenv, ctab);
    k2_fin1<<<1, 512>>>(w1, g1, beta1);
    k2b_bsplit<<<HID * HID / 256, 256>>>(w2);
    dim3 g3(4, B_ROWS / 128);
    k3b_gemm<<<g3, 256, GEMM_SMEM>>>();
    k5_fin2<<<HID, 256>>>(g2, beta2);
    k6_out<<<4096, 256>>>(w3, b3, out);
}

// round 7
// speedup vs baseline: 1.0769x; 1.0769x over previous
#include <cuda_runtime.h>
#include <cuda_fp16.h>
#include <math.h>
#include <stdint.h>

#define B_ROWS 262144
#define HID 512
#define NB1 512
#define NPART 2048         // GEMM bm count = stats partials

// ---------------- device scratch ----------------
__device__ __half g_A[(size_t)B_ROWS * HID];      // t1 fp16 (256 MB)
__device__ __half g_B[HID * HID];                 // [n][k] = w2[k][n] fp16
__device__ __half g_h2h[(size_t)B_ROWS * HID];    // h2 fp16 (256 MB)
__device__ float  g_feat[B_ROWS * 4];
__device__ double g_p1[NB1 * 14];
__device__ float  g_W1eff[4 * HID];
__device__ float  g_shift1[HID];                  // folded: beta1 - meanX @ W1eff
__device__ float  g_p2s[(size_t)NPART * HID];
__device__ float  g_p2q[(size_t)NPART * HID];
__device__ float  g_a2[HID];
__device__ float  g_d2[HID];

// ---------------- PTX helpers (sm_80-level, safe at compute_103) ----------------
__device__ __forceinline__ uint32_t smem_u32(const void* p) {
    uint32_t a;
    asm("{ .reg .u64 t; cvta.to.shared.u64 t, %1; cvt.u32.u64 %0, t; }" : "=r"(a) : "l"(p));
    return a;
}
#define CP_ASYNC16(dst, src) \
    asm volatile("cp.async.cg.shared.global [%0], [%1], 16;" :: "r"(dst), "l"(src) : "memory")
#define CP_COMMIT() asm volatile("cp.async.commit_group;" ::: "memory")
#define CP_WAIT(n)  asm volatile("cp.async.wait_group %0;" :: "n"(n) : "memory")
#define LDSM_X4(r0, r1, r2, r3, addr) \
    asm volatile("ldmatrix.sync.aligned.m8n8.x4.shared.b16 {%0,%1,%2,%3}, [%4];" \
        : "=r"(r0), "=r"(r1), "=r"(r2), "=r"(r3) : "r"(addr))
#define MMA16816F16(d, a, b0, b1) \
    asm volatile("mma.sync.aligned.m16n8k16.row.col.f32.f16.f16.f32 " \
        "{%0,%1,%2,%3},{%4,%5,%6,%7},{%8,%9},{%0,%1,%2,%3};" \
        : "+f"((d)[0]), "+f"((d)[1]), "+f"((d)[2]), "+f"((d)[3]) \
        : "r"((a)[0]), "r"((a)[1]), "r"((a)[2]), "r"((a)[3]), "r"(b0), "r"(b1))

__device__ __forceinline__ float ftanh(float x) {        // accurate path (k6)
    x = fminf(fmaxf(x, -9.0f), 9.0f);
    float e = __expf(2.0f * x);
    return __fdividef(e - 1.0f, e + 1.0f);
}
__device__ __forceinline__ float htanh(float x) {        // HW approx (pre-fp16 rounding)
    float y;
    asm("tanh.approx.f32 %0, %1;" : "=f"(y) : "f"(x));
    return y;
}

// ---------------- K1: features + (sum, second-moment) partials ----------------
__global__ void k1_feat(const float* __restrict__ x,
                        const float* __restrict__ tset,
                        const float* __restrict__ tenv,
                        const float* __restrict__ ctab)
{
    __shared__ float sxs[9], sys[14], stab[9 * 14];
    int tid = threadIdx.x;
    if (tid < 9)   sxs[tid] = tset[tid];
    if (tid < 14)  sys[tid] = tenv[tid];
    if (tid < 126) stab[tid] = ctab[tid];
    __syncthreads();

    double s0 = 0, s1 = 0, s2 = 0, s3 = 0;
    double m00 = 0, m01 = 0, m02 = 0, m03 = 0, m11 = 0, m12 = 0, m13 = 0,
           m22 = 0, m23 = 0, m33 = 0;

    for (int r = blockIdx.x * blockDim.x + tid; r < B_ROWS; r += gridDim.x * blockDim.x) {
        const float* xr = x + (size_t)r * 15;
        float amb = xr[1], fl = xr[2], fr = xr[3];
        float incar = xr[8], breq = xr[9], cin = xr[10];

        float yq = fminf(fmaxf(amb, sys[0]), sys[13]);
        int j = 0;
        #pragma unroll
        for (int k = 1; k <= 12; k++) j += (sys[k] <= yq);
        float y0 = sys[j], y1 = sys[j + 1];
        float ty = (yq - y0) / (y1 - y0);

        auto interp = [&](float xq) -> float {
            xq = fminf(fmaxf(xq, sxs[0]), sxs[8]);
            int i = 0;
            #pragma unroll
            for (int k = 1; k <= 7; k++) i += (sxs[k] <= xq);
            float x0 = sxs[i], x1 = sxs[i + 1];
            float tx = (xq - x0) / (x1 - x0);
            float f00 = stab[i * 14 + j],       f01 = stab[i * 14 + j + 1];
            float f10 = stab[(i + 1) * 14 + j], f11 = stab[(i + 1) * 14 + j + 1];
            return f00 * (1.f - tx) * (1.f - ty) + f10 * tx * (1.f - ty)
                 + f01 * (1.f - tx) * ty        + f11 * tx * ty;
        };

        float f0 = interp(fl) - incar;
        float f1 = interp(fr) - incar;
        float f2 = amb;
        float f3 = breq - cin;
        *(float4*)&g_feat[(size_t)r * 4] = make_float4(f0, f1, f2, f3);

        s0 += f0; s1 += f1; s2 += f2; s3 += f3;
        m00 += (double)f0 * f0; m01 += (double)f0 * f1; m02 += (double)f0 * f2; m03 += (double)f0 * f3;
        m11 += (double)f1 * f1; m12 += (double)f1 * f2; m13 += (double)f1 * f3;
        m22 += (double)f2 * f2; m23 += (double)f2 * f3; m33 += (double)f3 * f3;
    }

    __shared__ double red[256];
    double vals[14] = {s0, s1, s2, s3, m00, m01, m02, m03, m11, m12, m13, m22, m23, m33};
    for (int q = 0; q < 14; q++) {
        red[tid] = vals[q];
        __syncthreads();
        for (int off = 128; off > 0; off >>= 1) {
            if (tid < off) red[tid] += red[tid + off];
            __syncthreads();
        }
        if (tid == 0) g_p1[blockIdx.x * 14 + q] = red[0];
        __syncthreads();
    }
}

// ---------------- K2: finalize layer-1 BN fold (mean folded into shift) ----------------
__global__ void k2_fin1(const float* __restrict__ w1,
                        const float* __restrict__ g1,
                        const float* __restrict__ beta1)
{
    __shared__ double acc[14];
    __shared__ float C[4][4];
    __shared__ float sMean[4];
    int tid = threadIdx.x;
    if (tid < 14) {
        double s = 0;
        for (int p = 0; p < NB1; p++) s += g_p1[p * 14 + tid];
        acc[tid] = s;
    }
    __syncthreads();
    if (tid == 0) {
        double inv = 1.0 / (double)B_ROWS;
        double mm[4];
        for (int a = 0; a < 4; a++) { mm[a] = acc[a] * inv; sMean[a] = (float)mm[a]; }
        double M[4][4];
        int idx = 4;
        for (int a = 0; a < 4; a++)
            for (int b = a; b < 4; b++) M[a][b] = acc[idx++] * inv;
        for (int a = 0; a < 4; a++)
            for (int b = a; b < 4; b++) {
                double c = M[a][b] - mm[a] * mm[b];
                C[a][b] = (float)c; C[b][a] = (float)c;
            }
    }
    __syncthreads();
    if (tid < HID) {
        float w[4];
        for (int a = 0; a < 4; a++) w[a] = w1[a * HID + tid];
        float var = 0.f;
        for (int a = 0; a < 4; a++)
            for (int b = 0; b < 4; b++) var += w[a] * C[a][b] * w[b];
        float s = g1[tid] * rsqrtf(var + 1e-5f);
        float we[4];
        for (int a = 0; a < 4; a++) { we[a] = w[a] * s; g_W1eff[a * HID + tid] = we[a]; }
        g_shift1[tid] = beta1[tid]
                      - (sMean[0] * we[0] + sMean[1] * we[1] + sMean[2] * we[2] + sMean[3] * we[3]);
    }
}

// ---------------- K2b: transpose w2 -> B [n][k] fp16 ----------------
__global__ void k2b_bsplit(const float* __restrict__ w2)
{
    int idx = blockIdx.x * 256 + threadIdx.x;
    int n = idx >> 9, k = idx & 511;
    g_B[n * HID + k] = __float2half_rn(w2[k * HID + n]);
}

// ---------------- K3a: t1 = tanh(feat @ W1eff + shift) -> fp16 ----------------
__global__ void __launch_bounds__(256) k3a_layer1()
{
    int tid = threadIdx.x;
    int jc = (tid & 127) * 4;
    int r0 = blockIdx.x * 16 + (tid >> 7) * 8;

    float4 w0 = *(const float4*)&g_W1eff[0 * HID + jc];
    float4 w1v = *(const float4*)&g_W1eff[1 * HID + jc];
    float4 w2v = *(const float4*)&g_W1eff[2 * HID + jc];
    float4 w3v = *(const float4*)&g_W1eff[3 * HID + jc];
    float4 sh = *(const float4*)&g_shift1[jc];

    #pragma unroll
    for (int rr = 0; rr < 8; rr++) {
        int r = r0 + rr;
        float4 f = *(const float4*)&g_feat[(size_t)r * 4];
        float v0 = f.x * w0.x + f.y * w1v.x + f.z * w2v.x + f.w * w3v.x + sh.x;
        float v1 = f.x * w0.y + f.y * w1v.y + f.z * w2v.y + f.w * w3v.y + sh.y;
        float v2 = f.x * w0.z + f.y * w1v.z + f.z * w2v.z + f.w * w3v.z + sh.z;
        float v3 = f.x * w0.w + f.y * w1v.w + f.z * w2v.w + f.w * w3v.w + sh.w;
        __half2 p0 = __floats2half2_rn(htanh(v0), htanh(v1));
        __half2 p1 = __floats2half2_rn(htanh(v2), htanh(v3));
        uint2 pk = make_uint2(*(uint32_t*)&p0, *(uint32_t*)&p1);
        *(uint2*)(g_A + (size_t)r * HID + jc) = pk;
    }
}

// ---------------- K3b: h2 = t1 @ w2 (fp16 mma.sync, 4-stage pipeline) + stats ----------------
// CTA tile 128x128, 8 warps (warp tile 32x64), KSTAGE=32, 4-deep cp.async ring.
#define KSTAGE 32
#define ROWPAD 80                      // 64B data + 16B pad (conflict-free ldmatrix)
#define ATILE_B (128 * ROWPAD)         // 10240
#define OFF_A 0
#define OFF_B ATILE_B
#define STAGEB (2 * ATILE_B)           // 20480
#define NSTG 4
#define KITERS (HID / KSTAGE)          // 16
#define GEMM_SMEM (NSTG * STAGEB)      // 81920
#define RSTRIDE 136                    // epilogue staging row stride in halves (272B)
#define SST_OFF 36864                  // stats scratch offset (bytes)

__global__ void __launch_bounds__(256, 2) k3b_gemm()
{
    extern __shared__ char smem[];
    const uint32_t sb = smem_u32(smem);
    const int tid = threadIdx.x;
    const int wid = tid >> 5, lane = tid & 31;
    const int bn = blockIdx.x, bm = blockIdx.y;
    const size_t arow0 = (size_t)bm * 128;
    const int ncol0 = bn * 128;

    auto issue_stage = [&](int st) {
        uint32_t stg = sb + (st & (NSTG - 1)) * STAGEB;
        int kk = st * KSTAGE;
        #pragma unroll
        for (int h = 0; h < 2; h++) {
            int idx = tid + h * 256;          // 512 chunks of 16B per operand
            int r = idx >> 2, c = idx & 3;
            uint32_t doff = (uint32_t)r * ROWPAD + c * 16;
            CP_ASYNC16(stg + OFF_A + doff, g_A + (arow0 + r) * HID + kk + c * 8);
            CP_ASYNC16(stg + OFF_B + doff, g_B + (size_t)(ncol0 + r) * HID + kk + c * 8);
        }
    };

    // prologue: 3 stages in flight
    issue_stage(0); CP_COMMIT();
    issue_stage(1); CP_COMMIT();
    issue_stage(2); CP_COMMIT();

    const int warp_m = wid & 3;
    const int warp_n = wid >> 2;

    float acc[2][8][4];
    #pragma unroll
    for (int i = 0; i < 2; i++)
        #pragma unroll
        for (int j = 0; j < 8; j++)
            #pragma unroll
            for (int q = 0; q < 4; q++) acc[i][j][q] = 0.f;

    const int a_row = warp_m * 32 + (lane & 15);
    const uint32_t a_koff = (lane >> 4) * 16;
    const int b_row = warp_n * 64 + (lane & 7) + ((lane >> 4) & 1) * 8;
    const uint32_t b_koff = ((lane >> 3) & 1) * 16;

    for (int s = 0; s < KITERS; s++) {
        CP_WAIT(2);            // group s complete (uniform commits) -> stage s ready
        __syncthreads();       // also protects ring-buffer reuse

        if (s + 3 < KITERS) issue_stage(s + 3);
        CP_COMMIT();           // uniform commit (may be empty)

        uint32_t stg = sb + (s & (NSTG - 1)) * STAGEB;

        // front-load BOTH k-steps' fragments, then burst 32 HMMA
        uint32_t f0a[2][4], f0b[4][4], f1a[2][4], f1b[4][4];
        #pragma unroll
        for (int im = 0; im < 2; im++) {
            uint32_t aa = stg + OFF_A + (uint32_t)(a_row + im * 16) * ROWPAD + a_koff;
            LDSM_X4(f0a[im][0], f0a[im][1], f0a[im][2], f0a[im][3], aa);
            LDSM_X4(f1a[im][0], f1a[im][1], f1a[im][2], f1a[im][3], aa + 32);
        }
        #pragma unroll
        for (int ng = 0; ng < 4; ng++) {
            uint32_t ba = stg + OFF_B + (uint32_t)(b_row + ng * 16) * ROWPAD + b_koff;
            LDSM_X4(f0b[ng][0], f0b[ng][1], f0b[ng][2], f0b[ng][3], ba);
            LDSM_X4(f1b[ng][0], f1b[ng][1], f1b[ng][2], f1b[ng][3], ba + 32);
        }
        #pragma unroll
        for (int ng = 0; ng < 4; ng++) {
            #pragma unroll
            for (int im = 0; im < 2; im++) {
                MMA16816F16(acc[im][ng * 2 + 0], f0a[im], f0b[ng][0], f0b[ng][1]);
                MMA16816F16(acc[im][ng * 2 + 1], f0a[im], f0b[ng][2], f0b[ng][3]);
            }
        }
        #pragma unroll
        for (int ng = 0; ng < 4; ng++) {
            #pragma unroll
            for (int im = 0; im < 2; im++) {
                MMA16816F16(acc[im][ng * 2 + 0], f1a[im], f1b[ng][0], f1b[ng][1]);
                MMA16816F16(acc[im][ng * 2 + 1], f1a[im], f1b[ng][2], f1b[ng][3]);
            }
        }
    }
    __syncthreads();   // all smem reads done; reuse for epilogue

    // ---- epilogue 1: pack fp16 into smem staging (conflict-free) ----
    __half* hst = (__half*)smem;          // 128 rows x RSTRIDE halves
    #pragma unroll
    for (int im = 0; im < 2; im++) {
        #pragma unroll
        for (int half = 0; half < 2; half++) {
            int row = warp_m * 32 + im * 16 + (lane >> 2) + half * 8;
            int colb = warp_n * 64 + (lane & 3) * 2;
            #pragma unroll
            for (int ng2 = 0; ng2 < 8; ng2++) {
                __half2 hv = __floats2half2_rn(acc[im][ng2][2 * half], acc[im][ng2][2 * half + 1]);
                *(__half2*)&hst[row * RSTRIDE + colb + ng2 * 8] = hv;
            }
        }
    }

    // ---- epilogue 2: fused column sum/sumsq partials ----
    float* sst = (float*)(smem + SST_OFF);        // [4 warp_m][128 col][2]
    #pragma unroll
    for (int ng2 = 0; ng2 < 8; ng2++) {
        #pragma unroll
        for (int e = 0; e < 2; e++) {
            float s = 0.f, q = 0.f;
            #pragma unroll
            for (int im = 0; im < 2; im++) {
                #pragma unroll
                for (int half = 0; half < 2; half++) {
                    float v = acc[im][ng2][2 * half + e];
                    s += v; q += v * v;
                }
            }
            #pragma unroll
            for (int off = 4; off < 32; off <<= 1) {
                s += __shfl_xor_sync(0xffffffffu, s, off);
                q += __shfl_xor_sync(0xffffffffu, q, off);
            }
            if (lane < 4) {
                int col = warp_n * 64 + ng2 * 8 + lane * 2 + e;
                sst[(warp_m * 128 + col) * 2 + 0] = s;
                sst[(warp_m * 128 + col) * 2 + 1] = q;
            }
        }
    }
    __syncthreads();

    // ---- epilogue 3: coalesced fp16 stores from staging ----
    #pragma unroll
    for (int it = 0; it < 8; it++) {
        int g = it * 256 + tid;               // 2048 chunks of 16B
        int row = g >> 4, ch = g & 15;
        uint4 v = *(uint4*)&hst[row * RSTRIDE + ch * 8];
        *(uint4*)(g_h2h + (arow0 + row) * HID + ncol0 + ch * 8) = v;
    }

    // ---- epilogue 4: reduce stats across warp_m, write partials ----
    if (tid < 256) {
        int col = tid >> 1, sq = tid & 1;
        float v = sst[(0 * 128 + col) * 2 + sq] + sst[(1 * 128 + col) * 2 + sq]
                + sst[(2 * 128 + col) * 2 + sq] + sst[(3 * 128 + col) * 2 + sq];
        size_t gidx = (size_t)bm * HID + bn * 128 + col;
        if (sq == 0) g_p2s[gidx] = v; else g_p2q[gidx] = v;
    }
}

// ---------------- K5: finalize layer-2 BN fold (one block per column) ----------------
__global__ void k5_fin2(const float* __restrict__ g2, const float* __restrict__ beta2)
{
    int c = blockIdx.x;
    int t = threadIdx.x;
    double s = 0, q = 0;
    for (int p = t; p < NPART; p += 256) {
        s += (double)g_p2s[(size_t)p * HID + c];
        q += (double)g_p2q[(size_t)p * HID + c];
    }
    __shared__ double rs[256], rq[256];
    rs[t] = s; rq[t] = q;
    __syncthreads();
    for (int off = 128; off > 0; off >>= 1) {
        if (t < off) { rs[t] += rs[t + off]; rq[t] += rq[t + off]; }
        __syncthreads();
    }
    if (t == 0) {
        double mu  = rs[0] / (double)B_ROWS;
        double var = rq[0] / (double)B_ROWS - mu * mu;
        float a = g2[c] * rsqrtf((float)var + 1e-5f);
        g_a2[c] = a;
        g_d2[c] = beta2[c] - (float)mu * a;
    }
}

// ---------------- K6: out = tanh(a2*h2 + d2) @ w3 + b3 (register-resident consts) ----------------
__global__ void __launch_bounds__(256) k6_out(const float* __restrict__ w3,
                                              const float* __restrict__ b3,
                                              float* __restrict__ out)
{
    int t = threadIdx.x;
    int warp = t >> 5, lane = t & 31;
    float bias = b3[0];

    float ra[16], rd[16], rw[16];
    #pragma unroll
    for (int p = 0; p < 2; p++) {
        int c0 = p * 256 + lane * 8;
        #pragma unroll
        for (int u = 0; u < 8; u++) {
            ra[p * 8 + u] = g_a2[c0 + u];
            rd[p * 8 + u] = g_d2[c0 + u];
            rw[p * 8 + u] = w3[c0 + u];
        }
    }

    int gw = blockIdx.x * 8 + warp;
    int stride = gridDim.x * 8;
    for (int r = gw; r < B_ROWS; r += stride) {
        const __half* row = g_h2h + (size_t)r * HID;
        float acc = 0.f;
        #pragma unroll
        for (int p = 0; p < 2; p++) {
            int c0 = p * 256 + lane * 8;
            uint4 v = *(const uint4*)(row + c0);
            float2 f0 = __half22float2(*(__half2*)&v.x);
            float2 f1 = __half22float2(*(__half2*)&v.y);
            float2 f2 = __half22float2(*(__half2*)&v.z);
            float2 f3 = __half22float2(*(__half2*)&v.w);
            float hv[8] = {f0.x, f0.y, f1.x, f1.y, f2.x, f2.y, f3.x, f3.y};
            #pragma unroll
            for (int u = 0; u < 8; u++) {
                int q = p * 8 + u;
                acc += ftanh(fmaf(ra[q], hv[u], rd[q])) * rw[q];
            }
        }
        #pragma unroll
        for (int off = 16; off; off >>= 1) acc += __shfl_xor_sync(0xffffffffu, acc, off);
        if (lane == 0) out[r] = acc + bias;
    }
}

// ---------------- launch ----------------
extern "C" void kernel_launch(void* const* d_in, const int* in_sizes, int n_in,
                              void* d_out, int out_size)
{
    const float* x     = (const float*)d_in[0];
    const float* tset  = (const float*)d_in[1];
    const float* tenv  = (const float*)d_in[2];
    const float* ctab  = (const float*)d_in[3];
    const float* w1    = (const float*)d_in[4];
    const float* g1    = (const float*)d_in[6];
    const float* beta1 = (const float*)d_in[7];
    const float* w2    = (const float*)d_in[8];
    const float* g2    = (const float*)d_in[10];
    const float* beta2 = (const float*)d_in[11];
    const float* w3    = (const float*)d_in[12];
    const float* b3    = (const float*)d_in[13];
    float* out = (float*)d_out;

    static bool attr_set = false;
    if (!attr_set) {
        cudaFuncSetAttribute(k3b_gemm, cudaFuncAttributeMaxDynamicSharedMemorySize, GEMM_SMEM);
        attr_set = true;
    }

    k1_feat<<<NB1, 256>>>(x, tset, tenv, ctab);
    k2_fin1<<<1, 512>>>(w1, g1, beta1);
    k2b_bsplit<<<HID * HID / 256, 256>>>(w2);
    k3a_layer1<<<B_ROWS / 16, 256>>>();
    dim3 g3(4, B_ROWS / 128);
    k3b_gemm<<<g3, 256, GEMM_SMEM>>>();
    k5_fin2<<<HID, 256>>>(g2, beta2);
    k6_out<<<4096, 256>>>(w3, b3, out);
}

// round 8
// speedup vs baseline: 1.1541x; 1.0717x over previous
#include <cuda_runtime.h>
#include <cuda_fp16.h>
#include <math.h>
#include <stdint.h>

#define B_ROWS 262144
#define HID 512
#define NB1 512
#define NPART 2048         // GEMM bm count = stats partials

// ---------------- device scratch ----------------
__device__ __half g_A[(size_t)B_ROWS * HID];      // t1 fp16 (256 MB)
__device__ __half g_B[HID * HID];                 // [n][k] = w2[k][n] fp16
__device__ __half g_h2h[(size_t)B_ROWS * HID];    // h2 fp16 (256 MB)
__device__ float  g_feat[B_ROWS * 4];
__device__ double g_p1[NB1 * 14];
__device__ float  g_W1eff[4 * HID];
__device__ float  g_shift1[HID];                  // folded: beta1 - meanX @ W1eff
__device__ float  g_p2s[(size_t)NPART * HID];
__device__ float  g_p2q[(size_t)NPART * HID];
__device__ float  g_a2[HID];
__device__ float  g_d2[HID];

// ---------------- PTX helpers (sm_80-level, safe at compute_103) ----------------
__device__ __forceinline__ uint32_t smem_u32(const void* p) {
    uint32_t a;
    asm("{ .reg .u64 t; cvta.to.shared.u64 t, %1; cvt.u32.u64 %0, t; }" : "=r"(a) : "l"(p));
    return a;
}
#define CP_ASYNC16(dst, src) \
    asm volatile("cp.async.cg.shared.global [%0], [%1], 16;" :: "r"(dst), "l"(src) : "memory")
#define CP_COMMIT() asm volatile("cp.async.commit_group;" ::: "memory")
#define CP_WAIT(n)  asm volatile("cp.async.wait_group %0;" :: "n"(n) : "memory")
#define LDSM_X4(r0, r1, r2, r3, addr) \
    asm volatile("ldmatrix.sync.aligned.m8n8.x4.shared.b16 {%0,%1,%2,%3}, [%4];" \
        : "=r"(r0), "=r"(r1), "=r"(r2), "=r"(r3) : "r"(addr))
#define MMA16816F16(d, a, b0, b1) \
    asm volatile("mma.sync.aligned.m16n8k16.row.col.f32.f16.f16.f32 " \
        "{%0,%1,%2,%3},{%4,%5,%6,%7},{%8,%9},{%0,%1,%2,%3};" \
        : "+f"((d)[0]), "+f"((d)[1]), "+f"((d)[2]), "+f"((d)[3]) \
        : "r"((a)[0]), "r"((a)[1]), "r"((a)[2]), "r"((a)[3]), "r"(b0), "r"(b1))

__device__ __forceinline__ float ftanh(float x) {        // accurate path (k6)
    x = fminf(fmaxf(x, -9.0f), 9.0f);
    float e = __expf(2.0f * x);
    return __fdividef(e - 1.0f, e + 1.0f);
}
__device__ __forceinline__ float htanh(float x) {        // HW approx (pre-fp16 rounding)
    float y;
    asm("tanh.approx.f32 %0, %1;" : "=f"(y) : "f"(x));
    return y;
}

// ---------------- K1: features + (sum, second-moment) partials ----------------
__global__ void k1_feat(const float* __restrict__ x,
                        const float* __restrict__ tset,
                        const float* __restrict__ tenv,
                        const float* __restrict__ ctab)
{
    __shared__ float sxs[9], sys[14], stab[9 * 14];
    int tid = threadIdx.x;
    if (tid < 9)   sxs[tid] = tset[tid];
    if (tid < 14)  sys[tid] = tenv[tid];
    if (tid < 126) stab[tid] = ctab[tid];
    __syncthreads();

    double s0 = 0, s1 = 0, s2 = 0, s3 = 0;
    double m00 = 0, m01 = 0, m02 = 0, m03 = 0, m11 = 0, m12 = 0, m13 = 0,
           m22 = 0, m23 = 0, m33 = 0;

    for (int r = blockIdx.x * blockDim.x + tid; r < B_ROWS; r += gridDim.x * blockDim.x) {
        const float* xr = x + (size_t)r * 15;
        float amb = xr[1], fl = xr[2], fr = xr[3];
        float incar = xr[8], breq = xr[9], cin = xr[10];

        float yq = fminf(fmaxf(amb, sys[0]), sys[13]);
        int j = 0;
        #pragma unroll
        for (int k = 1; k <= 12; k++) j += (sys[k] <= yq);
        float y0 = sys[j], y1 = sys[j + 1];
        float ty = (yq - y0) / (y1 - y0);

        auto interp = [&](float xq) -> float {
            xq = fminf(fmaxf(xq, sxs[0]), sxs[8]);
            int i = 0;
            #pragma unroll
            for (int k = 1; k <= 7; k++) i += (sxs[k] <= xq);
            float x0 = sxs[i], x1 = sxs[i + 1];
            float tx = (xq - x0) / (x1 - x0);
            float f00 = stab[i * 14 + j],       f01 = stab[i * 14 + j + 1];
            float f10 = stab[(i + 1) * 14 + j], f11 = stab[(i + 1) * 14 + j + 1];
            return f00 * (1.f - tx) * (1.f - ty) + f10 * tx * (1.f - ty)
                 + f01 * (1.f - tx) * ty        + f11 * tx * ty;
        };

        float f0 = interp(fl) - incar;
        float f1 = interp(fr) - incar;
        float f2 = amb;
        float f3 = breq - cin;
        *(float4*)&g_feat[(size_t)r * 4] = make_float4(f0, f1, f2, f3);

        s0 += f0; s1 += f1; s2 += f2; s3 += f3;
        m00 += (double)f0 * f0; m01 += (double)f0 * f1; m02 += (double)f0 * f2; m03 += (double)f0 * f3;
        m11 += (double)f1 * f1; m12 += (double)f1 * f2; m13 += (double)f1 * f3;
        m22 += (double)f2 * f2; m23 += (double)f2 * f3; m33 += (double)f3 * f3;
    }

    __shared__ double red[256];
    double vals[14] = {s0, s1, s2, s3, m00, m01, m02, m03, m11, m12, m13, m22, m23, m33};
    for (int q = 0; q < 14; q++) {
        red[tid] = vals[q];
        __syncthreads();
        for (int off = 128; off > 0; off >>= 1) {
            if (tid < off) red[tid] += red[tid + off];
            __syncthreads();
        }
        if (tid == 0) g_p1[blockIdx.x * 14 + q] = red[0];
        __syncthreads();
    }
}

// ---------------- K2: finalize layer-1 BN fold (mean folded into shift) ----------------
__global__ void k2_fin1(const float* __restrict__ w1,
                        const float* __restrict__ g1,
                        const float* __restrict__ beta1)
{
    __shared__ double acc[14];
    __shared__ float C[4][4];
    __shared__ float sMean[4];
    int tid = threadIdx.x;
    if (tid < 14) {
        double s = 0;
        for (int p = 0; p < NB1; p++) s += g_p1[p * 14 + tid];
        acc[tid] = s;
    }
    __syncthreads();
    if (tid == 0) {
        double inv = 1.0 / (double)B_ROWS;
        double mm[4];
        for (int a = 0; a < 4; a++) { mm[a] = acc[a] * inv; sMean[a] = (float)mm[a]; }
        double M[4][4];
        int idx = 4;
        for (int a = 0; a < 4; a++)
            for (int b = a; b < 4; b++) M[a][b] = acc[idx++] * inv;
        for (int a = 0; a < 4; a++)
            for (int b = a; b < 4; b++) {
                double c = M[a][b] - mm[a] * mm[b];
                C[a][b] = (float)c; C[b][a] = (float)c;
            }
    }
    __syncthreads();
    if (tid < HID) {
        float w[4];
        for (int a = 0; a < 4; a++) w[a] = w1[a * HID + tid];
        float var = 0.f;
        for (int a = 0; a < 4; a++)
            for (int b = 0; b < 4; b++) var += w[a] * C[a][b] * w[b];
        float s = g1[tid] * rsqrtf(var + 1e-5f);
        float we[4];
        for (int a = 0; a < 4; a++) { we[a] = w[a] * s; g_W1eff[a * HID + tid] = we[a]; }
        g_shift1[tid] = beta1[tid]
                      - (sMean[0] * we[0] + sMean[1] * we[1] + sMean[2] * we[2] + sMean[3] * we[3]);
    }
}

// ---------------- K2b: transpose w2 -> B [n][k] fp16 ----------------
__global__ void k2b_bsplit(const float* __restrict__ w2)
{
    int idx = blockIdx.x * 256 + threadIdx.x;
    int n = idx >> 9, k = idx & 511;
    g_B[n * HID + k] = __float2half_rn(w2[k * HID + n]);
}

// ---------------- K3a: t1 = tanh(feat @ W1eff + shift) -> fp16 ----------------
__global__ void __launch_bounds__(256) k3a_layer1()
{
    int tid = threadIdx.x;
    int jc = (tid & 127) * 4;
    int r0 = blockIdx.x * 16 + (tid >> 7) * 8;

    float4 w0 = *(const float4*)&g_W1eff[0 * HID + jc];
    float4 w1v = *(const float4*)&g_W1eff[1 * HID + jc];
    float4 w2v = *(const float4*)&g_W1eff[2 * HID + jc];
    float4 w3v = *(const float4*)&g_W1eff[3 * HID + jc];
    float4 sh = *(const float4*)&g_shift1[jc];

    #pragma unroll
    for (int rr = 0; rr < 8; rr++) {
        int r = r0 + rr;
        float4 f = *(const float4*)&g_feat[(size_t)r * 4];
        float v0 = f.x * w0.x + f.y * w1v.x + f.z * w2v.x + f.w * w3v.x + sh.x;
        float v1 = f.x * w0.y + f.y * w1v.y + f.z * w2v.y + f.w * w3v.y + sh.y;
        float v2 = f.x * w0.z + f.y * w1v.z + f.z * w2v.z + f.w * w3v.z + sh.z;
        float v3 = f.x * w0.w + f.y * w1v.w + f.z * w2v.w + f.w * w3v.w + sh.w;
        __half2 p0 = __floats2half2_rn(htanh(v0), htanh(v1));
        __half2 p1 = __floats2half2_rn(htanh(v2), htanh(v3));
        uint2 pk = make_uint2(*(uint32_t*)&p0, *(uint32_t*)&p1);
        *(uint2*)(g_A + (size_t)r * HID + jc) = pk;
    }
}

// ---------------- K3b: h2 = t1 @ w2 (fp16 mma.sync) + fused column stats ----------------
// CTA tile 128x128, 8 warps (warp tile 32x64), KSTAGE=64, 3-deep cp.async ring,
// register fragment double-buffering across the per-stage barrier.
#define KSTAGE 64
#define ROWPAD 144                     // 128B data + 16B pad (conflict-free ldmatrix)
#define OFF_A 0
#define OFF_B (128 * ROWPAD)           // 18432
#define STAGEB (256 * ROWPAD)          // 36864
#define NSTG 3
#define GEMM_SMEM (NSTG * STAGEB)      // 110592 (2 CTAs/SM = 221 KB)
#define RSTRIDE 136                    // epilogue staging row stride in halves (272B)
#define SST_OFF 36864                  // stats scratch (buffer-1 region, post-loop only)

__global__ void __launch_bounds__(256, 2) k3b_gemm()
{
    extern __shared__ char smem[];
    const uint32_t sb = smem_u32(smem);
    const int tid = threadIdx.x;
    const int wid = tid >> 5, lane = tid & 31;
    const int bn = blockIdx.x, bm = blockIdx.y;
    const size_t arow0 = (size_t)bm * 128;
    const int ncol0 = bn * 128;

    auto issue_stage = [&](int st) {
        uint32_t stg = sb + (st % NSTG) * STAGEB;
        int kk = st * KSTAGE;
        #pragma unroll
        for (int h = 0; h < 8; h++) {
            int idx = tid + h * 256;
            int r = (idx & 1023) >> 3, c = idx & 7;
            uint32_t doff = (uint32_t)r * ROWPAD + c * 16;
            if (idx < 1024) {
                CP_ASYNC16(stg + OFF_A + doff, g_A + (arow0 + r) * HID + kk + c * 8);
            } else {
                CP_ASYNC16(stg + OFF_B + doff, g_B + (size_t)(ncol0 + r) * HID + kk + c * 8);
            }
        }
    };

    // prologue: 2 stages in flight (issue distance 2)
    issue_stage(0); CP_COMMIT();
    issue_stage(1); CP_COMMIT();

    const int warp_m = wid & 3;
    const int warp_n = wid >> 2;

    float acc[2][8][4];
    #pragma unroll
    for (int i = 0; i < 2; i++)
        #pragma unroll
        for (int j = 0; j < 8; j++)
            #pragma unroll
            for (int q = 0; q < 4; q++) acc[i][j][q] = 0.f;

    const int a_row = warp_m * 32 + (lane & 15);
    const uint32_t a_koff = (lane >> 4) * 16;
    const int b_row = warp_n * 64 + (lane & 7) + ((lane >> 4) & 1) * 8;
    const uint32_t b_koff = ((lane >> 3) & 1) * 16;

    // register fragment double buffers
    uint32_t fa[2][2][4];      // [buf][im][reg]
    uint32_t fb[2][4][4];      // [buf][ng][reg]

#define LOAD_FRAGS(STG, KS, BUF) do {                                          \
        uint32_t _kb = (uint32_t)(KS) * 32;                                    \
        uint32_t _aa = (STG) + OFF_A + (uint32_t)a_row * ROWPAD + _kb + a_koff;\
        LDSM_X4(fa[BUF][0][0], fa[BUF][0][1], fa[BUF][0][2], fa[BUF][0][3], _aa);              \
        LDSM_X4(fa[BUF][1][0], fa[BUF][1][1], fa[BUF][1][2], fa[BUF][1][3], _aa + 16 * ROWPAD);\
        uint32_t _bb = (STG) + OFF_B + (uint32_t)b_row * ROWPAD + _kb + b_koff;\
        LDSM_X4(fb[BUF][0][0], fb[BUF][0][1], fb[BUF][0][2], fb[BUF][0][3], _bb);              \
        LDSM_X4(fb[BUF][1][0], fb[BUF][1][1], fb[BUF][1][2], fb[BUF][1][3], _bb + 16 * ROWPAD);\
        LDSM_X4(fb[BUF][2][0], fb[BUF][2][1], fb[BUF][2][2], fb[BUF][2][3], _bb + 32 * ROWPAD);\
        LDSM_X4(fb[BUF][3][0], fb[BUF][3][1], fb[BUF][3][2], fb[BUF][3][3], _bb + 48 * ROWPAD);\
    } while (0)

#define MMA_KS(BUF) do {                                                       \
        _Pragma("unroll")                                                      \
        for (int ng = 0; ng < 4; ng++) {                                       \
            _Pragma("unroll")                                                  \
            for (int im = 0; im < 2; im++) {                                   \
                MMA16816F16(acc[im][ng * 2 + 0], fa[BUF][im], fb[BUF][ng][0], fb[BUF][ng][1]); \
                MMA16816F16(acc[im][ng * 2 + 1], fa[BUF][im], fb[BUF][ng][2], fb[BUF][ng][3]); \
            }                                                                  \
        }                                                                      \
    } while (0)

    for (int s = 0; s < 8; s++) {
        CP_WAIT(0);                 // buffers s AND s+1 complete (issue distance 2)
        __syncthreads();            // publish loads + protect ring reuse

        uint32_t stg  = sb + (s % NSTG) * STAGEB;
        uint32_t nstg = sb + ((s + 1) % NSTG) * STAGEB;

        if (s == 0) LOAD_FRAGS(stg, 0, 0);   // first stage: no preloaded frags yet

        #pragma unroll
        for (int ks = 0; ks < 4; ks++) {
            const int cb = ks & 1;
            // prefetch next k-step (or next stage's ks0) while HMMA of current ks issues
            if (ks < 3)      LOAD_FRAGS(stg, ks + 1, cb ^ 1);
            else if (s < 7)  LOAD_FRAGS(nstg, 0, cb ^ 1);
            if (ks == 0 && s + 2 < 8) { issue_stage(s + 2); CP_COMMIT(); }
            MMA_KS(cb);
        }
    }
    __syncthreads();   // all smem reads done; reuse for epilogue

    // ---- epilogue 1: pack fp16 into smem staging (conflict-free) ----
    __half* hst = (__half*)smem;          // 128 rows x RSTRIDE halves
    #pragma unroll
    for (int im = 0; im < 2; im++) {
        #pragma unroll
        for (int half = 0; half < 2; half++) {
            int row = warp_m * 32 + im * 16 + (lane >> 2) + half * 8;
            int colb = warp_n * 64 + (lane & 3) * 2;
            #pragma unroll
            for (int ng2 = 0; ng2 < 8; ng2++) {
                __half2 hv = __floats2half2_rn(acc[im][ng2][2 * half], acc[im][ng2][2 * half + 1]);
                *(__half2*)&hst[row * RSTRIDE + colb + ng2 * 8] = hv;
            }
        }
    }

    // ---- epilogue 2: fused column sum/sumsq partials ----
    float* sst = (float*)(smem + SST_OFF);        // [4 warp_m][128 col][2]
    #pragma unroll
    for (int ng2 = 0; ng2 < 8; ng2++) {
        #pragma unroll
        for (int e = 0; e < 2; e++) {
            float s = 0.f, q = 0.f;
            #pragma unroll
            for (int im = 0; im < 2; im++) {
                #pragma unroll
                for (int half = 0; half < 2; half++) {
                    float v = acc[im][ng2][2 * half + e];
                    s += v; q += v * v;
                }
            }
            #pragma unroll
            for (int off = 4; off < 32; off <<= 1) {
                s += __shfl_xor_sync(0xffffffffu, s, off);
                q += __shfl_xor_sync(0xffffffffu, q, off);
            }
            if (lane < 4) {
                int col = warp_n * 64 + ng2 * 8 + lane * 2 + e;
                sst[(warp_m * 128 + col) * 2 + 0] = s;
                sst[(warp_m * 128 + col) * 2 + 1] = q;
            }
        }
    }
    __syncthreads();

    // ---- epilogue 3: coalesced fp16 stores from staging ----
    #pragma unroll
    for (int it = 0; it < 8; it++) {
        int g = it * 256 + tid;               // 2048 chunks of 16B
        int row = g >> 4, ch = g & 15;
        uint4 v = *(uint4*)&hst[row * RSTRIDE + ch * 8];
        *(uint4*)(g_h2h + (arow0 + row) * HID + ncol0 + ch * 8) = v;
    }

    // ---- epilogue 4: reduce stats across warp_m, write partials ----
    if (tid < 256) {
        int col = tid >> 1, sq = tid & 1;
        float v = sst[(0 * 128 + col) * 2 + sq] + sst[(1 * 128 + col) * 2 + sq]
                + sst[(2 * 128 + col) * 2 + sq] + sst[(3 * 128 + col) * 2 + sq];
        size_t gidx = (size_t)bm * HID + bn * 128 + col;
        if (sq == 0) g_p2s[gidx] = v; else g_p2q[gidx] = v;
    }
#undef LOAD_FRAGS
#undef MMA_KS
}

// ---------------- K5: finalize layer-2 BN fold (one block per column) ----------------
__global__ void k5_fin2(const float* __restrict__ g2, const float* __restrict__ beta2)
{
    int c = blockIdx.x;
    int t = threadIdx.x;
    double s = 0, q = 0;
    for (int p = t; p < NPART; p += 256) {
        s += (double)g_p2s[(size_t)p * HID + c];
        q += (double)g_p2q[(size_t)p * HID + c];
    }
    __shared__ double rs[256], rq[256];
    rs[t] = s; rq[t] = q;
    __syncthreads();
    for (int off = 128; off > 0; off >>= 1) {
        if (t < off) { rs[t] += rs[t + off]; rq[t] += rq[t + off]; }
        __syncthreads();
    }
    if (t == 0) {
        double mu  = rs[0] / (double)B_ROWS;
        double var = rq[0] / (double)B_ROWS - mu * mu;
        float a = g2[c] * rsqrtf((float)var + 1e-5f);
        g_a2[c] = a;
        g_d2[c] = beta2[c] - (float)mu * a;
    }
}

// ---------------- K6: out = tanh(a2*h2 + d2) @ w3 + b3 (register-resident consts) ----------------
__global__ void __launch_bounds__(256) k6_out(const float* __restrict__ w3,
                                              const float* __restrict__ b3,
                                              float* __restrict__ out)
{
    int t = threadIdx.x;
    int warp = t >> 5, lane = t & 31;
    float bias = b3[0];

    float ra[16], rd[16], rw[16];
    #pragma unroll
    for (int p = 0; p < 2; p++) {
        int c0 = p * 256 + lane * 8;
        #pragma unroll
        for (int u = 0; u < 8; u++) {
            ra[p * 8 + u] = g_a2[c0 + u];
            rd[p * 8 + u] = g_d2[c0 + u];
            rw[p * 8 + u] = w3[c0 + u];
        }
    }

    int gw = blockIdx.x * 8 + warp;
    int stride = gridDim.x * 8;
    for (int r = gw; r < B_ROWS; r += stride) {
        const __half* row = g_h2h + (size_t)r * HID;
        float acc = 0.f;
        #pragma unroll
        for (int p = 0; p < 2; p++) {
            int c0 = p * 256 + lane * 8;
            uint4 v = *(const uint4*)(row + c0);
            float2 f0 = __half22float2(*(__half2*)&v.x);
            float2 f1 = __half22float2(*(__half2*)&v.y);
            float2 f2 = __half22float2(*(__half2*)&v.z);
            float2 f3 = __half22float2(*(__half2*)&v.w);
            float hv[8] = {f0.x, f0.y, f1.x, f1.y, f2.x, f2.y, f3.x, f3.y};
            #pragma unroll
            for (int u = 0; u < 8; u++) {
                int q = p * 8 + u;
                acc += ftanh(fmaf(ra[q], hv[u], rd[q])) * rw[q];
            }
        }
        #pragma unroll
        for (int off = 16; off; off >>= 1) acc += __shfl_xor_sync(0xffffffffu, acc, off);
        if (lane == 0) out[r] = acc + bias;
    }
}

// ---------------- launch ----------------
extern "C" void kernel_launch(void* const* d_in, const int* in_sizes, int n_in,
                              void* d_out, int out_size)
{
    const float* x     = (const float*)d_in[0];
    const float* tset  = (const float*)d_in[1];
    const float* tenv  = (const float*)d_in[2];
    const float* ctab  = (const float*)d_in[3];
    const float* w1    = (const float*)d_in[4];
    const float* g1    = (const float*)d_in[6];
    const float* beta1 = (const float*)d_in[7];
    const float* w2    = (const float*)d_in[8];
    const float* g2    = (const float*)d_in[10];
    const float* beta2 = (const float*)d_in[11];
    const float* w3    = (const float*)d_in[12];
    const float* b3    = (const float*)d_in[13];
    float* out = (float*)d_out;

    static bool attr_set = false;
    if (!attr_set) {
        cudaFuncSetAttribute(k3b_gemm, cudaFuncAttributeMaxDynamicSharedMemorySize, GEMM_SMEM);
        attr_set = true;
    }

    k1_feat<<<NB1, 256>>>(x, tset, tenv, ctab);
    k2_fin1<<<1, 512>>>(w1, g1, beta1);
    k2b_bsplit<<<HID * HID / 256, 256>>>(w2);
    k3a_layer1<<<B_ROWS / 16, 256>>>();
    dim3 g3(4, B_ROWS / 128);
    k3b_gemm<<<g3, 256, GEMM_SMEM>>>();
    k5_fin2<<<HID, 256>>>(g2, beta2);
    k6_out<<<4096, 256>>>(w3, b3, out);
}

// round 9
// speedup vs baseline: 1.1898x; 1.0309x over previous
#include <cuda_runtime.h>
#include <cuda_fp16.h>
#include <math.h>
#include <stdint.h>

#define B_ROWS 262144
#define HID 512
#define NB1 512
#define NPART 2048         // GEMM bm count = stats partials

// ---------------- device scratch ----------------
__device__ __half g_A[(size_t)B_ROWS * HID];      // t1 fp16 (256 MB)
__device__ __half g_B[HID * HID];                 // [n][k] = w2[k][n] fp16
__device__ __half g_h2h[(size_t)B_ROWS * HID];    // h2 fp16 (256 MB)
__device__ float  g_feat[B_ROWS * 4];
__device__ double g_p1[NB1 * 14];
__device__ float  g_W1eff[4 * HID];
__device__ float  g_shift1[HID];                  // folded: beta1 - meanX @ W1eff
__device__ float  g_p2s[(size_t)NPART * HID];
__device__ float  g_p2q[(size_t)NPART * HID];
__device__ float  g_a2[HID];
__device__ float  g_d2[HID];

// ---------------- PTX helpers (sm_80-level, safe at compute_103) ----------------
__device__ __forceinline__ uint32_t smem_u32(const void* p) {
    uint32_t a;
    asm("{ .reg .u64 t; cvta.to.shared.u64 t, %1; cvt.u32.u64 %0, t; }" : "=r"(a) : "l"(p));
    return a;
}
#define CP_ASYNC16(dst, src) \
    asm volatile("cp.async.cg.shared.global [%0], [%1], 16;" :: "r"(dst), "l"(src) : "memory")
#define CP_COMMIT() asm volatile("cp.async.commit_group;" ::: "memory")
#define CP_WAIT(n)  asm volatile("cp.async.wait_group %0;" :: "n"(n) : "memory")
#define LDSM_X4(r0, r1, r2, r3, addr) \
    asm volatile("ldmatrix.sync.aligned.m8n8.x4.shared.b16 {%0,%1,%2,%3}, [%4];" \
        : "=r"(r0), "=r"(r1), "=r"(r2), "=r"(r3) : "r"(addr))
#define MMA16816F16(d, a, b0, b1) \
    asm volatile("mma.sync.aligned.m16n8k16.row.col.f32.f16.f16.f32 " \
        "{%0,%1,%2,%3},{%4,%5,%6,%7},{%8,%9},{%0,%1,%2,%3};" \
        : "+f"((d)[0]), "+f"((d)[1]), "+f"((d)[2]), "+f"((d)[3]) \
        : "r"((a)[0]), "r"((a)[1]), "r"((a)[2]), "r"((a)[3]), "r"(b0), "r"(b1))

__device__ __forceinline__ float ftanh(float x) {        // accurate path (k6)
    x = fminf(fmaxf(x, -9.0f), 9.0f);
    float e = __expf(2.0f * x);
    return __fdividef(e - 1.0f, e + 1.0f);
}
__device__ __forceinline__ float htanh(float x) {        // HW approx (pre-fp16 rounding)
    float y;
    asm("tanh.approx.f32 %0, %1;" : "=f"(y) : "f"(x));
    return y;
}

// ---------------- K1: features + (sum, second-moment) partials ----------------
__global__ void k1_feat(const float* __restrict__ x,
                        const float* __restrict__ tset,
                        const float* __restrict__ tenv,
                        const float* __restrict__ ctab)
{
    __shared__ float sxs[9], sys[14], stab[9 * 14];
    int tid = threadIdx.x;
    if (tid < 9)   sxs[tid] = tset[tid];
    if (tid < 14)  sys[tid] = tenv[tid];
    if (tid < 126) stab[tid] = ctab[tid];
    __syncthreads();

    double s0 = 0, s1 = 0, s2 = 0, s3 = 0;
    double m00 = 0, m01 = 0, m02 = 0, m03 = 0, m11 = 0, m12 = 0, m13 = 0,
           m22 = 0, m23 = 0, m33 = 0;

    for (int r = blockIdx.x * blockDim.x + tid; r < B_ROWS; r += gridDim.x * blockDim.x) {
        const float* xr = x + (size_t)r * 15;
        float amb = xr[1], fl = xr[2], fr = xr[3];
        float incar = xr[8], breq = xr[9], cin = xr[10];

        float yq = fminf(fmaxf(amb, sys[0]), sys[13]);
        int j = 0;
        #pragma unroll
        for (int k = 1; k <= 12; k++) j += (sys[k] <= yq);
        float y0 = sys[j], y1 = sys[j + 1];
        float ty = (yq - y0) / (y1 - y0);

        auto interp = [&](float xq) -> float {
            xq = fminf(fmaxf(xq, sxs[0]), sxs[8]);
            int i = 0;
            #pragma unroll
            for (int k = 1; k <= 7; k++) i += (sxs[k] <= xq);
            float x0 = sxs[i], x1 = sxs[i + 1];
            float tx = (xq - x0) / (x1 - x0);
            float f00 = stab[i * 14 + j],       f01 = stab[i * 14 + j + 1];
            float f10 = stab[(i + 1) * 14 + j], f11 = stab[(i + 1) * 14 + j + 1];
            return f00 * (1.f - tx) * (1.f - ty) + f10 * tx * (1.f - ty)
                 + f01 * (1.f - tx) * ty        + f11 * tx * ty;
        };

        float f0 = interp(fl) - incar;
        float f1 = interp(fr) - incar;
        float f2 = amb;
        float f3 = breq - cin;
        *(float4*)&g_feat[(size_t)r * 4] = make_float4(f0, f1, f2, f3);

        s0 += f0; s1 += f1; s2 += f2; s3 += f3;
        m00 += (double)f0 * f0; m01 += (double)f0 * f1; m02 += (double)f0 * f2; m03 += (double)f0 * f3;
        m11 += (double)f1 * f1; m12 += (double)f1 * f2; m13 += (double)f1 * f3;
        m22 += (double)f2 * f2; m23 += (double)f2 * f3; m33 += (double)f3 * f3;
    }

    __shared__ double red[256];
    double vals[14] = {s0, s1, s2, s3, m00, m01, m02, m03, m11, m12, m13, m22, m23, m33};
    for (int q = 0; q < 14; q++) {
        red[tid] = vals[q];
        __syncthreads();
        for (int off = 128; off > 0; off >>= 1) {
            if (tid < off) red[tid] += red[tid + off];
            __syncthreads();
        }
        if (tid == 0) g_p1[blockIdx.x * 14 + q] = red[0];
        __syncthreads();
    }
}

// ---------------- K2: finalize layer-1 BN fold (mean folded into shift) ----------------
__global__ void k2_fin1(const float* __restrict__ w1,
                        const float* __restrict__ g1,
                        const float* __restrict__ beta1)
{
    __shared__ double acc[14];
    __shared__ float C[4][4];
    __shared__ float sMean[4];
    int tid = threadIdx.x;
    if (tid < 14) {
        double s = 0;
        for (int p = 0; p < NB1; p++) s += g_p1[p * 14 + tid];
        acc[tid] = s;
    }
    __syncthreads();
    if (tid == 0) {
        double inv = 1.0 / (double)B_ROWS;
        double mm[4];
        for (int a = 0; a < 4; a++) { mm[a] = acc[a] * inv; sMean[a] = (float)mm[a]; }
        double M[4][4];
        int idx = 4;
        for (int a = 0; a < 4; a++)
            for (int b = a; b < 4; b++) M[a][b] = acc[idx++] * inv;
        for (int a = 0; a < 4; a++)
            for (int b = a; b < 4; b++) {
                double c = M[a][b] - mm[a] * mm[b];
                C[a][b] = (float)c; C[b][a] = (float)c;
            }
    }
    __syncthreads();
    if (tid < HID) {
        float w[4];
        for (int a = 0; a < 4; a++) w[a] = w1[a * HID + tid];
        float var = 0.f;
        for (int a = 0; a < 4; a++)
            for (int b = 0; b < 4; b++) var += w[a] * C[a][b] * w[b];
        float s = g1[tid] * rsqrtf(var + 1e-5f);
        float we[4];
        for (int a = 0; a < 4; a++) { we[a] = w[a] * s; g_W1eff[a * HID + tid] = we[a]; }
        g_shift1[tid] = beta1[tid]
                      - (sMean[0] * we[0] + sMean[1] * we[1] + sMean[2] * we[2] + sMean[3] * we[3]);
    }
}

// ---------------- K2b: transpose w2 -> B [n][k] fp16 ----------------
__global__ void k2b_bsplit(const float* __restrict__ w2)
{
    int idx = blockIdx.x * 256 + threadIdx.x;
    int n = idx >> 9, k = idx & 511;
    g_B[n * HID + k] = __float2half_rn(w2[k * HID + n]);
}

// ---------------- K3a: t1 = tanh(feat @ W1eff + shift) -> fp16 ----------------
__global__ void __launch_bounds__(256) k3a_layer1()
{
    int tid = threadIdx.x;
    int jc = (tid & 127) * 4;
    int r0 = blockIdx.x * 16 + (tid >> 7) * 8;

    float4 w0 = *(const float4*)&g_W1eff[0 * HID + jc];
    float4 w1v = *(const float4*)&g_W1eff[1 * HID + jc];
    float4 w2v = *(const float4*)&g_W1eff[2 * HID + jc];
    float4 w3v = *(const float4*)&g_W1eff[3 * HID + jc];
    float4 sh = *(const float4*)&g_shift1[jc];

    #pragma unroll
    for (int rr = 0; rr < 8; rr++) {
        int r = r0 + rr;
        float4 f = *(const float4*)&g_feat[(size_t)r * 4];
        float v0 = f.x * w0.x + f.y * w1v.x + f.z * w2v.x + f.w * w3v.x + sh.x;
        float v1 = f.x * w0.y + f.y * w1v.y + f.z * w2v.y + f.w * w3v.y + sh.y;
        float v2 = f.x * w0.z + f.y * w1v.z + f.z * w2v.z + f.w * w3v.z + sh.z;
        float v3 = f.x * w0.w + f.y * w1v.w + f.z * w2v.w + f.w * w3v.w + sh.w;
        __half2 p0 = __floats2half2_rn(htanh(v0), htanh(v1));
        __half2 p1 = __floats2half2_rn(htanh(v2), htanh(v3));
        uint2 pk = make_uint2(*(uint32_t*)&p0, *(uint32_t*)&p1);
        *(uint2*)(g_A + (size_t)r * HID + jc) = pk;
    }
}

// ---------------- K3b: h2 = t1 @ w2 (fp16 mma.sync) + fused column stats ----------------
// CTA tile 128x128, 4 warps (warp tile 64x64 -> lower smem read amplification),
// KSTAGE=64, 3-deep cp.async ring, uniform commits + CP_WAIT(1).
#define KSTAGE 64
#define ROWPAD 144                     // 128B data + 16B pad (conflict-free ldmatrix)
#define OFF_A 0
#define OFF_B (128 * ROWPAD)           // 18432
#define STAGEB (256 * ROWPAD)          // 36864
#define NSTG 3
#define GEMM_SMEM (NSTG * STAGEB)      // 110592 (2 CTAs/SM = 221 KB)
#define RSTRIDE 136                    // epilogue staging row stride in halves (272B)
#define SST_OFF 36864                  // stats scratch (buffer-1 region, post-loop only)
#define GTHREADS 128

__global__ void __launch_bounds__(GTHREADS, 2) k3b_gemm()
{
    extern __shared__ char smem[];
    const uint32_t sb = smem_u32(smem);
    const int tid = threadIdx.x;
    const int wid = tid >> 5, lane = tid & 31;
    const int bn = blockIdx.x, bm = blockIdx.y;
    const size_t arow0 = (size_t)bm * 128;
    const int ncol0 = bn * 128;

    auto issue_stage = [&](int st) {
        uint32_t stg = sb + (st % NSTG) * STAGEB;
        int kk = st * KSTAGE;
        #pragma unroll
        for (int h = 0; h < 16; h++) {
            int idx = tid + h * GTHREADS;       // 2048 chunks of 16B
            int r = (idx & 1023) >> 3, c = idx & 7;
            uint32_t doff = (uint32_t)r * ROWPAD + c * 16;
            if (idx < 1024) {
                CP_ASYNC16(stg + OFF_A + doff, g_A + (arow0 + r) * HID + kk + c * 8);
            } else {
                CP_ASYNC16(stg + OFF_B + doff, g_B + (size_t)(ncol0 + r) * HID + kk + c * 8);
            }
        }
    };

    // prologue: 2 stages in flight
    issue_stage(0); CP_COMMIT();
    issue_stage(1); CP_COMMIT();

    const int warp_m = wid & 1;        // 2 warp rows of 64
    const int warp_n = wid >> 1;       // 2 warp cols of 64

    float acc[4][8][4];
    #pragma unroll
    for (int i = 0; i < 4; i++)
        #pragma unroll
        for (int j = 0; j < 8; j++)
            #pragma unroll
            for (int q = 0; q < 4; q++) acc[i][j][q] = 0.f;

    const int a_row = warp_m * 64 + (lane & 15);
    const uint32_t a_koff = (lane >> 4) * 16;
    const int b_row = warp_n * 64 + (lane & 7) + ((lane >> 4) & 1) * 8;
    const uint32_t b_koff = ((lane >> 3) & 1) * 16;

    for (int s = 0; s < 8; s++) {
        CP_WAIT(1);                 // buffer s complete; s+1 may still fly
        __syncthreads();            // publish loads + protect ring reuse

        uint32_t stg = sb + (s % NSTG) * STAGEB;

        #pragma unroll
        for (int ks = 0; ks < 4; ks++) {
            uint32_t kb = ks * 32;
            uint32_t fa[4][4], fb[4][4];
            #pragma unroll
            for (int im = 0; im < 4; im++) {
                uint32_t aa = stg + OFF_A + (uint32_t)(a_row + im * 16) * ROWPAD + kb + a_koff;
                LDSM_X4(fa[im][0], fa[im][1], fa[im][2], fa[im][3], aa);
            }
            #pragma unroll
            for (int ng4 = 0; ng4 < 4; ng4++) {
                uint32_t bb = stg + OFF_B + (uint32_t)(b_row + ng4 * 16) * ROWPAD + kb + b_koff;
                LDSM_X4(fb[ng4][0], fb[ng4][1], fb[ng4][2], fb[ng4][3], bb);
            }
            if (ks == 0) {
                if (s + 2 < 8) issue_stage(s + 2);
                CP_COMMIT();        // uniform commit (may be empty)
            }
            #pragma unroll
            for (int ng4 = 0; ng4 < 4; ng4++) {
                #pragma unroll
                for (int im = 0; im < 4; im++) {
                    MMA16816F16(acc[im][ng4 * 2 + 0], fa[im], fb[ng4][0], fb[ng4][1]);
                    MMA16816F16(acc[im][ng4 * 2 + 1], fa[im], fb[ng4][2], fb[ng4][3]);
                }
            }
        }
    }
    CP_WAIT(0);
    __syncthreads();   // all smem reads done; reuse for epilogue

    // ---- epilogue 1: pack fp16 into smem staging (conflict-free) ----
    __half* hst = (__half*)smem;          // 128 rows x RSTRIDE halves
    #pragma unroll
    for (int im = 0; im < 4; im++) {
        #pragma unroll
        for (int half = 0; half < 2; half++) {
            int row = warp_m * 64 + im * 16 + (lane >> 2) + half * 8;
            int colb = warp_n * 64 + (lane & 3) * 2;
            #pragma unroll
            for (int ng2 = 0; ng2 < 8; ng2++) {
                __half2 hv = __floats2half2_rn(acc[im][ng2][2 * half], acc[im][ng2][2 * half + 1]);
                *(__half2*)&hst[row * RSTRIDE + colb + ng2 * 8] = hv;
            }
        }
    }

    // ---- epilogue 2: fused column sum/sumsq partials ----
    float* sst = (float*)(smem + SST_OFF);        // [2 warp_m][128 col][2]
    #pragma unroll
    for (int ng2 = 0; ng2 < 8; ng2++) {
        #pragma unroll
        for (int e = 0; e < 2; e++) {
            float s = 0.f, q = 0.f;
            #pragma unroll
            for (int im = 0; im < 4; im++) {
                #pragma unroll
                for (int half = 0; half < 2; half++) {
                    float v = acc[im][ng2][2 * half + e];
                    s += v; q += v * v;
                }
            }
            #pragma unroll
            for (int off = 4; off < 32; off <<= 1) {
                s += __shfl_xor_sync(0xffffffffu, s, off);
                q += __shfl_xor_sync(0xffffffffu, q, off);
            }
            if (lane < 4) {
                int col = warp_n * 64 + ng2 * 8 + lane * 2 + e;
                sst[(warp_m * 128 + col) * 2 + 0] = s;
                sst[(warp_m * 128 + col) * 2 + 1] = q;
            }
        }
    }
    __syncthreads();

    // ---- epilogue 3: coalesced fp16 stores from staging ----
    #pragma unroll
    for (int it = 0; it < 16; it++) {
        int g = it * GTHREADS + tid;          // 2048 chunks of 16B
        int row = g >> 4, ch = g & 15;
        uint4 v = *(uint4*)&hst[row * RSTRIDE + ch * 8];
        *(uint4*)(g_h2h + (arow0 + row) * HID + ncol0 + ch * 8) = v;
    }

    // ---- epilogue 4: reduce stats across warp_m, write partials ----
    #pragma unroll
    for (int g = tid; g < 256; g += GTHREADS) {
        int col = g >> 1, sq = g & 1;
        float v = sst[(0 * 128 + col) * 2 + sq] + sst[(1 * 128 + col) * 2 + sq];
        size_t gidx = (size_t)bm * HID + bn * 128 + col;
        if (sq == 0) g_p2s[gidx] = v; else g_p2q[gidx] = v;
    }
}

// ---------------- K5: finalize layer-2 BN fold (one block per column) ----------------
__global__ void k5_fin2(const float* __restrict__ g2, const float* __restrict__ beta2)
{
    int c = blockIdx.x;
    int t = threadIdx.x;
    double s = 0, q = 0;
    for (int p = t; p < NPART; p += 256) {
        s += (double)g_p2s[(size_t)p * HID + c];
        q += (double)g_p2q[(size_t)p * HID + c];
    }
    __shared__ double rs[256], rq[256];
    rs[t] = s; rq[t] = q;
    __syncthreads();
    for (int off = 128; off > 0; off >>= 1) {
        if (t < off) { rs[t] += rs[t + off]; rq[t] += rq[t + off]; }
        __syncthreads();
    }
    if (t == 0) {
        double mu  = rs[0] / (double)B_ROWS;
        double var = rq[0] / (double)B_ROWS - mu * mu;
        float a = g2[c] * rsqrtf((float)var + 1e-5f);
        g_a2[c] = a;
        g_d2[c] = beta2[c] - (float)mu * a;
    }
}

// ---------------- K6: out = tanh(a2*h2 + d2) @ w3 + b3 (register-resident consts) ----------------
__global__ void __launch_bounds__(256) k6_out(const float* __restrict__ w3,
                                              const float* __restrict__ b3,
                                              float* __restrict__ out)
{
    int t = threadIdx.x;
    int warp = t >> 5, lane = t & 31;
    float bias = b3[0];

    float ra[16], rd[16], rw[16];
    #pragma unroll
    for (int p = 0; p < 2; p++) {
        int c0 = p * 256 + lane * 8;
        #pragma unroll
        for (int u = 0; u < 8; u++) {
            ra[p * 8 + u] = g_a2[c0 + u];
            rd[p * 8 + u] = g_d2[c0 + u];
            rw[p * 8 + u] = w3[c0 + u];
        }
    }

    int gw = blockIdx.x * 8 + warp;
    int stride = gridDim.x * 8;
    for (int r = gw; r < B_ROWS; r += stride) {
        const __half* row = g_h2h + (size_t)r * HID;
        float acc = 0.f;
        #pragma unroll
        for (int p = 0; p < 2; p++) {
            int c0 = p * 256 + lane * 8;
            uint4 v = *(const uint4*)(row + c0);
            float2 f0 = __half22float2(*(__half2*)&v.x);
            float2 f1 = __half22float2(*(__half2*)&v.y);
            float2 f2 = __half22float2(*(__half2*)&v.z);
            float2 f3 = __half22float2(*(__half2*)&v.w);
            float hv[8] = {f0.x, f0.y, f1.x, f1.y, f2.x, f2.y, f3.x, f3.y};
            #pragma unroll
            for (int u = 0; u < 8; u++) {
                int q = p * 8 + u;
                acc += ftanh(fmaf(ra[q], hv[u], rd[q])) * rw[q];
            }
        }
        #pragma unroll
        for (int off = 16; off; off >>= 1) acc += __shfl_xor_sync(0xffffffffu, acc, off);
        if (lane == 0) out[r] = acc + bias;
    }
}

// ---------------- launch ----------------
extern "C" void kernel_launch(void* const* d_in, const int* in_sizes, int n_in,
                              void* d_out, int out_size)
{
    const float* x     = (const float*)d_in[0];
    const float* tset  = (const float*)d_in[1];
    const float* tenv  = (const float*)d_in[2];
    const float* ctab  = (const float*)d_in[3];
    const float* w1    = (const float*)d_in[4];
    const float* g1    = (const float*)d_in[6];
    const float* beta1 = (const float*)d_in[7];
    const float* w2    = (const float*)d_in[8];
    const float* g2    = (const float*)d_in[10];
    const float* beta2 = (const float*)d_in[11];
    const float* w3    = (const float*)d_in[12];
    const float* b3    = (const float*)d_in[13];
    float* out = (float*)d_out;

    static bool attr_set = false;
    if (!attr_set) {
        cudaFuncSetAttribute(k3b_gemm, cudaFuncAttributeMaxDynamicSharedMemorySize, GEMM_SMEM);
        attr_set = true;
    }

    k1_feat<<<NB1, 256>>>(x, tset, tenv, ctab);
    k2_fin1<<<1, 512>>>(w1, g1, beta1);
    k2b_bsplit<<<HID * HID / 256, 256>>>(w2);
    k3a_layer1<<<B_ROWS / 16, 256>>>();
    dim3 g3(4, B_ROWS / 128);
    k3b_gemm<<<g3, GTHREADS, GEMM_SMEM>>>();
    k5_fin2<<<HID, 256>>>(g2, beta2);
    k6_out<<<4096, 256>>>(w3, b3, out);
}

// round 10
// speedup vs baseline: 1.2170x; 1.0229x over previous
#include <cuda_runtime.h>
#include <cuda_fp16.h>
#include <math.h>
#include <stdint.h>

#define B_ROWS 262144
#define HID 512
#define NB1 512
#define NPART 2048         // GEMM bm count = stats partials

// ---------------- device scratch ----------------
__device__ __half g_A[(size_t)B_ROWS * HID];      // t1 fp16 (256 MB)
__device__ __half g_B[HID * HID];                 // [n][k] = w2[k][n] fp16
__device__ __half g_h2h[(size_t)B_ROWS * HID];    // h2 fp16 (256 MB)
__device__ float  g_feat[B_ROWS * 4];
__device__ double g_p1[NB1 * 14];
__device__ float  g_W1eff[4 * HID];
__device__ float  g_shift1[HID];                  // folded: beta1 - meanX @ W1eff
__device__ float  g_p2s[(size_t)NPART * HID];
__device__ float  g_p2q[(size_t)NPART * HID];
__device__ float  g_a2[HID];
__device__ float  g_d2[HID];

// ---------------- PTX helpers (sm_80-level, safe at compute_103) ----------------
__device__ __forceinline__ uint32_t smem_u32(const void* p) {
    uint32_t a;
    asm("{ .reg .u64 t; cvta.to.shared.u64 t, %1; cvt.u32.u64 %0, t; }" : "=r"(a) : "l"(p));
    return a;
}
#define CP_ASYNC16(dst, src) \
    asm volatile("cp.async.cg.shared.global [%0], [%1], 16;" :: "r"(dst), "l"(src) : "memory")
#define CP_COMMIT() asm volatile("cp.async.commit_group;" ::: "memory")
#define CP_WAIT(n)  asm volatile("cp.async.wait_group %0;" :: "n"(n) : "memory")
#define LDSM_X4(r0, r1, r2, r3, addr) \
    asm volatile("ldmatrix.sync.aligned.m8n8.x4.shared.b16 {%0,%1,%2,%3}, [%4];" \
        : "=r"(r0), "=r"(r1), "=r"(r2), "=r"(r3) : "r"(addr))
#define MMA16816F16(d, a, b0, b1) \
    asm volatile("mma.sync.aligned.m16n8k16.row.col.f32.f16.f16.f32 " \
        "{%0,%1,%2,%3},{%4,%5,%6,%7},{%8,%9},{%0,%1,%2,%3};" \
        : "+f"((d)[0]), "+f"((d)[1]), "+f"((d)[2]), "+f"((d)[3]) \
        : "r"((a)[0]), "r"((a)[1]), "r"((a)[2]), "r"((a)[3]), "r"(b0), "r"(b1))

__device__ __forceinline__ float htanh(float x) {        // HW tanh (validated vs 1e-3 budget)
    float y;
    asm("tanh.approx.f32 %0, %1;" : "=f"(y) : "f"(x));
    return y;
}

// ---------------- K1: features + (sum, second-moment) partials ----------------
// Smem-staged coalesced loads of x (15 floats/row, 60B stride).
__global__ void __launch_bounds__(256) k1_feat(const float* __restrict__ x,
                                               const float* __restrict__ tset,
                                               const float* __restrict__ tenv,
                                               const float* __restrict__ ctab)
{
    __shared__ float sxs[9], sys[14], stab[9 * 14];
    __shared__ float srow[256][17];               // padded: stride 17 -> conflict-free
    int tid = threadIdx.x;
    if (tid < 9)   sxs[tid] = tset[tid];
    if (tid < 14)  sys[tid] = tenv[tid];
    if (tid < 126) stab[tid] = ctab[tid];
    __syncthreads();

    double s0 = 0, s1 = 0, s2 = 0, s3 = 0;
    double m00 = 0, m01 = 0, m02 = 0, m03 = 0, m11 = 0, m12 = 0, m13 = 0,
           m22 = 0, m23 = 0, m33 = 0;

    // each block owns 512 contiguous rows, processed in two 256-row chunks
    for (int chunk = 0; chunk < 2; chunk++) {
        int base = blockIdx.x * 512 + chunk * 256;
        // coalesced stage: 256 rows x 15 floats = 3840 contiguous floats
        const float* gsrc = x + (size_t)base * 15;
        for (int i = tid; i < 256 * 15; i += 256) {
            srow[i / 15][i % 15] = gsrc[i];
        }
        __syncthreads();

        int r = base + tid;
        float amb = srow[tid][1], fl = srow[tid][2], fr = srow[tid][3];
        float incar = srow[tid][8], breq = srow[tid][9], cin = srow[tid][10];

        float yq = fminf(fmaxf(amb, sys[0]), sys[13]);
        int j = 0;
        #pragma unroll
        for (int k = 1; k <= 12; k++) j += (sys[k] <= yq);
        float y0 = sys[j], y1 = sys[j + 1];
        float ty = (yq - y0) / (y1 - y0);

        auto interp = [&](float xq) -> float {
            xq = fminf(fmaxf(xq, sxs[0]), sxs[8]);
            int i = 0;
            #pragma unroll
            for (int k = 1; k <= 7; k++) i += (sxs[k] <= xq);
            float x0 = sxs[i], x1 = sxs[i + 1];
            float tx = (xq - x0) / (x1 - x0);
            float f00 = stab[i * 14 + j],       f01 = stab[i * 14 + j + 1];
            float f10 = stab[(i + 1) * 14 + j], f11 = stab[(i + 1) * 14 + j + 1];
            return f00 * (1.f - tx) * (1.f - ty) + f10 * tx * (1.f - ty)
                 + f01 * (1.f - tx) * ty        + f11 * tx * ty;
        };

        float f0 = interp(fl) - incar;
        float f1 = interp(fr) - incar;
        float f2 = amb;
        float f3 = breq - cin;
        *(float4*)&g_feat[(size_t)r * 4] = make_float4(f0, f1, f2, f3);

        s0 += f0; s1 += f1; s2 += f2; s3 += f3;
        m00 += (double)f0 * f0; m01 += (double)f0 * f1; m02 += (double)f0 * f2; m03 += (double)f0 * f3;
        m11 += (double)f1 * f1; m12 += (double)f1 * f2; m13 += (double)f1 * f3;
        m22 += (double)f2 * f2; m23 += (double)f2 * f3; m33 += (double)f3 * f3;
        __syncthreads();
    }

    __shared__ double red[256];
    double vals[14] = {s0, s1, s2, s3, m00, m01, m02, m03, m11, m12, m13, m22, m23, m33};
    for (int q = 0; q < 14; q++) {
        red[tid] = vals[q];
        __syncthreads();
        for (int off = 128; off > 0; off >>= 1) {
            if (tid < off) red[tid] += red[tid + off];
            __syncthreads();
        }
        if (tid == 0) g_p1[blockIdx.x * 14 + q] = red[0];
        __syncthreads();
    }
}

// ---------------- K2: finalize layer-1 BN fold (mean folded into shift) ----------------
__global__ void k2_fin1(const float* __restrict__ w1,
                        const float* __restrict__ g1,
                        const float* __restrict__ beta1)
{
    __shared__ double acc[14];
    __shared__ float C[4][4];
    __shared__ float sMean[4];
    int tid = threadIdx.x;
    if (tid < 14) {
        double s = 0;
        for (int p = 0; p < NB1; p++) s += g_p1[p * 14 + tid];
        acc[tid] = s;
    }
    __syncthreads();
    if (tid == 0) {
        double inv = 1.0 / (double)B_ROWS;
        double mm[4];
        for (int a = 0; a < 4; a++) { mm[a] = acc[a] * inv; sMean[a] = (float)mm[a]; }
        double M[4][4];
        int idx = 4;
        for (int a = 0; a < 4; a++)
            for (int b = a; b < 4; b++) M[a][b] = acc[idx++] * inv;
        for (int a = 0; a < 4; a++)
            for (int b = a; b < 4; b++) {
                double c = M[a][b] - mm[a] * mm[b];
                C[a][b] = (float)c; C[b][a] = (float)c;
            }
    }
    __syncthreads();
    if (tid < HID) {
        float w[4];
        for (int a = 0; a < 4; a++) w[a] = w1[a * HID + tid];
        float var = 0.f;
        for (int a = 0; a < 4; a++)
            for (int b = 0; b < 4; b++) var += w[a] * C[a][b] * w[b];
        float s = g1[tid] * rsqrtf(var + 1e-5f);
        float we[4];
        for (int a = 0; a < 4; a++) { we[a] = w[a] * s; g_W1eff[a * HID + tid] = we[a]; }
        g_shift1[tid] = beta1[tid]
                      - (sMean[0] * we[0] + sMean[1] * we[1] + sMean[2] * we[2] + sMean[3] * we[3]);
    }
}

// ---------------- K2b: transpose w2 -> B [n][k] fp16 ----------------
__global__ void k2b_bsplit(const float* __restrict__ w2)
{
    int idx = blockIdx.x * 256 + threadIdx.x;
    int n = idx >> 9, k = idx & 511;
    g_B[n * HID + k] = __float2half_rn(w2[k * HID + n]);
}

// ---------------- K3a: t1 = tanh(feat @ W1eff + shift) -> fp16 ----------------
__global__ void __launch_bounds__(256) k3a_layer1()
{
    int tid = threadIdx.x;
    int jc = (tid & 127) * 4;
    int r0 = blockIdx.x * 16 + (tid >> 7) * 8;

    float4 w0 = *(const float4*)&g_W1eff[0 * HID + jc];
    float4 w1v = *(const float4*)&g_W1eff[1 * HID + jc];
    float4 w2v = *(const float4*)&g_W1eff[2 * HID + jc];
    float4 w3v = *(const float4*)&g_W1eff[3 * HID + jc];
    float4 sh = *(const float4*)&g_shift1[jc];

    #pragma unroll
    for (int rr = 0; rr < 8; rr++) {
        int r = r0 + rr;
        float4 f = *(const float4*)&g_feat[(size_t)r * 4];
        float v0 = f.x * w0.x + f.y * w1v.x + f.z * w2v.x + f.w * w3v.x + sh.x;
        float v1 = f.x * w0.y + f.y * w1v.y + f.z * w2v.y + f.w * w3v.y + sh.y;
        float v2 = f.x * w0.z + f.y * w1v.z + f.z * w2v.z + f.w * w3v.z + sh.z;
        float v3 = f.x * w0.w + f.y * w1v.w + f.z * w2v.w + f.w * w3v.w + sh.w;
        __half2 p0 = __floats2half2_rn(htanh(v0), htanh(v1));
        __half2 p1 = __floats2half2_rn(htanh(v2), htanh(v3));
        uint2 pk = make_uint2(*(uint32_t*)&p0, *(uint32_t*)&p1);
        *(uint2*)(g_A + (size_t)r * HID + jc) = pk;
    }
}

// ---------------- K3b: h2 = t1 @ w2 (fp16 mma.sync) + fused column stats ----------------
// CTA tile 128x128, 4 warps (warp tile 64x64), KSTAGE=64, 3-deep cp.async ring.
#define KSTAGE 64
#define ROWPAD 144                     // 128B data + 16B pad (conflict-free ldmatrix)
#define OFF_A 0
#define OFF_B (128 * ROWPAD)           // 18432
#define STAGEB (256 * ROWPAD)          // 36864
#define NSTG 3
#define GEMM_SMEM (NSTG * STAGEB)      // 110592 (2 CTAs/SM = 221 KB)
#define RSTRIDE 136                    // epilogue staging row stride in halves (272B)
#define SST_OFF 36864                  // stats scratch (buffer-1 region, post-loop only)
#define GTHREADS 128

__global__ void __launch_bounds__(GTHREADS, 2) k3b_gemm()
{
    extern __shared__ char smem[];
    const uint32_t sb = smem_u32(smem);
    const int tid = threadIdx.x;
    const int wid = tid >> 5, lane = tid & 31;
    const int bn = blockIdx.x, bm = blockIdx.y;
    const size_t arow0 = (size_t)bm * 128;
    const int ncol0 = bn * 128;

    auto issue_stage = [&](int st) {
        uint32_t stg = sb + (st % NSTG) * STAGEB;
        int kk = st * KSTAGE;
        #pragma unroll
        for (int h = 0; h < 16; h++) {
            int idx = tid + h * GTHREADS;       // 2048 chunks of 16B
            int r = (idx & 1023) >> 3, c = idx & 7;
            uint32_t doff = (uint32_t)r * ROWPAD + c * 16;
            if (idx < 1024) {
                CP_ASYNC16(stg + OFF_A + doff, g_A + (arow0 + r) * HID + kk + c * 8);
            } else {
                CP_ASYNC16(stg + OFF_B + doff, g_B + (size_t)(ncol0 + r) * HID + kk + c * 8);
            }
        }
    };

    issue_stage(0); CP_COMMIT();
    issue_stage(1); CP_COMMIT();

    const int warp_m = wid & 1;        // 2 warp rows of 64
    const int warp_n = wid >> 1;       // 2 warp cols of 64

    float acc[4][8][4];
    #pragma unroll
    for (int i = 0; i < 4; i++)
        #pragma unroll
        for (int j = 0; j < 8; j++)
            #pragma unroll
            for (int q = 0; q < 4; q++) acc[i][j][q] = 0.f;

    const int a_row = warp_m * 64 + (lane & 15);
    const uint32_t a_koff = (lane >> 4) * 16;
    const int b_row = warp_n * 64 + (lane & 7) + ((lane >> 4) & 1) * 8;
    const uint32_t b_koff = ((lane >> 3) & 1) * 16;

    for (int s = 0; s < 8; s++) {
        CP_WAIT(1);
        __syncthreads();

        uint32_t stg = sb + (s % NSTG) * STAGEB;

        #pragma unroll
        for (int ks = 0; ks < 4; ks++) {
            uint32_t kb = ks * 32;
            uint32_t fa[4][4], fb[4][4];
            #pragma unroll
            for (int im = 0; im < 4; im++) {
                uint32_t aa = stg + OFF_A + (uint32_t)(a_row + im * 16) * ROWPAD + kb + a_koff;
                LDSM_X4(fa[im][0], fa[im][1], fa[im][2], fa[im][3], aa);
            }
            #pragma unroll
            for (int ng4 = 0; ng4 < 4; ng4++) {
                uint32_t bb = stg + OFF_B + (uint32_t)(b_row + ng4 * 16) * ROWPAD + kb + b_koff;
                LDSM_X4(fb[ng4][0], fb[ng4][1], fb[ng4][2], fb[ng4][3], bb);
            }
            if (ks == 0) {
                if (s + 2 < 8) issue_stage(s + 2);
                CP_COMMIT();
            }
            #pragma unroll
            for (int ng4 = 0; ng4 < 4; ng4++) {
                #pragma unroll
                for (int im = 0; im < 4; im++) {
                    MMA16816F16(acc[im][ng4 * 2 + 0], fa[im], fb[ng4][0], fb[ng4][1]);
                    MMA16816F16(acc[im][ng4 * 2 + 1], fa[im], fb[ng4][2], fb[ng4][3]);
                }
            }
        }
    }
    CP_WAIT(0);
    __syncthreads();

    // ---- epilogue 1: pack fp16 into smem staging (conflict-free) ----
    __half* hst = (__half*)smem;
    #pragma unroll
    for (int im = 0; im < 4; im++) {
        #pragma unroll
        for (int half = 0; half < 2; half++) {
            int row = warp_m * 64 + im * 16 + (lane >> 2) + half * 8;
            int colb = warp_n * 64 + (lane & 3) * 2;
            #pragma unroll
            for (int ng2 = 0; ng2 < 8; ng2++) {
                __half2 hv = __floats2half2_rn(acc[im][ng2][2 * half], acc[im][ng2][2 * half + 1]);
                *(__half2*)&hst[row * RSTRIDE + colb + ng2 * 8] = hv;
            }
        }
    }

    // ---- epilogue 2: fused column sum/sumsq partials ----
    float* sst = (float*)(smem + SST_OFF);
    #pragma unroll
    for (int ng2 = 0; ng2 < 8; ng2++) {
        #pragma unroll
        for (int e = 0; e < 2; e++) {
            float s = 0.f, q = 0.f;
            #pragma unroll
            for (int im = 0; im < 4; im++) {
                #pragma unroll
                for (int half = 0; half < 2; half++) {
                    float v = acc[im][ng2][2 * half + e];
                    s += v; q += v * v;
                }
            }
            #pragma unroll
            for (int off = 4; off < 32; off <<= 1) {
                s += __shfl_xor_sync(0xffffffffu, s, off);
                q += __shfl_xor_sync(0xffffffffu, q, off);
            }
            if (lane < 4) {
                int col = warp_n * 64 + ng2 * 8 + lane * 2 + e;
                sst[(warp_m * 128 + col) * 2 + 0] = s;
                sst[(warp_m * 128 + col) * 2 + 1] = q;
            }
        }
    }
    __syncthreads();

    // ---- epilogue 3: coalesced fp16 stores from staging ----
    #pragma unroll
    for (int it = 0; it < 16; it++) {
        int g = it * GTHREADS + tid;
        int row = g >> 4, ch = g & 15;
        uint4 v = *(uint4*)&hst[row * RSTRIDE + ch * 8];
        *(uint4*)(g_h2h + (arow0 + row) * HID + ncol0 + ch * 8) = v;
    }

    // ---- epilogue 4: reduce stats across warp_m, write partials ----
    #pragma unroll
    for (int g = tid; g < 256; g += GTHREADS) {
        int col = g >> 1, sq = g & 1;
        float v = sst[(0 * 128 + col) * 2 + sq] + sst[(1 * 128 + col) * 2 + sq];
        size_t gidx = (size_t)bm * HID + bn * 128 + col;
        if (sq == 0) g_p2s[gidx] = v; else g_p2q[gidx] = v;
    }
}

// ---------------- K5: finalize layer-2 BN fold (one block per column) ----------------
__global__ void k5_fin2(const float* __restrict__ g2, const float* __restrict__ beta2)
{
    int c = blockIdx.x;
    int t = threadIdx.x;
    double s = 0, q = 0;
    for (int p = t; p < NPART; p += 256) {
        s += (double)g_p2s[(size_t)p * HID + c];
        q += (double)g_p2q[(size_t)p * HID + c];
    }
    __shared__ double rs[256], rq[256];
    rs[t] = s; rq[t] = q;
    __syncthreads();
    for (int off = 128; off > 0; off >>= 1) {
        if (t < off) { rs[t] += rs[t + off]; rq[t] += rq[t + off]; }
        __syncthreads();
    }
    if (t == 0) {
        double mu  = rs[0] / (double)B_ROWS;
        double var = rq[0] / (double)B_ROWS - mu * mu;
        float a = g2[c] * rsqrtf((float)var + 1e-5f);
        g_a2[c] = a;
        g_d2[c] = beta2[c] - (float)mu * a;
    }
}

// ---------------- K6: out = tanh(a2*h2 + d2) @ w3 + b3 (HW tanh, reg consts) ----------------
__global__ void __launch_bounds__(256) k6_out(const float* __restrict__ w3,
                                              const float* __restrict__ b3,
                                              float* __restrict__ out)
{
    int t = threadIdx.x;
    int warp = t >> 5, lane = t & 31;
    float bias = b3[0];

    float ra[16], rd[16], rw[16];
    #pragma unroll
    for (int p = 0; p < 2; p++) {
        int c0 = p * 256 + lane * 8;
        #pragma unroll
        for (int u = 0; u < 8; u++) {
            ra[p * 8 + u] = g_a2[c0 + u];
            rd[p * 8 + u] = g_d2[c0 + u];
            rw[p * 8 + u] = w3[c0 + u];
        }
    }

    int gw = blockIdx.x * 8 + warp;
    int stride = gridDim.x * 8;
    for (int r = gw; r < B_ROWS; r += stride) {
        const __half* row = g_h2h + (size_t)r * HID;
        float acc = 0.f;
        #pragma unroll
        for (int p = 0; p < 2; p++) {
            int c0 = p * 256 + lane * 8;
            uint4 v = *(const uint4*)(row + c0);
            float2 f0 = __half22float2(*(__half2*)&v.x);
            float2 f1 = __half22float2(*(__half2*)&v.y);
            float2 f2 = __half22float2(*(__half2*)&v.z);
            float2 f3 = __half22float2(*(__half2*)&v.w);
            float hv[8] = {f0.x, f0.y, f1.x, f1.y, f2.x, f2.y, f3.x, f3.y};
            #pragma unroll
            for (int u = 0; u < 8; u++) {
                int q = p * 8 + u;
                acc += htanh(fmaf(ra[q], hv[u], rd[q])) * rw[q];
            }
        }
        #pragma unroll
        for (int off = 16; off; off >>= 1) acc += __shfl_xor_sync(0xffffffffu, acc, off);
        if (lane == 0) out[r] = acc + bias;
    }
}

// ---------------- launch ----------------
extern "C" void kernel_launch(void* const* d_in, const int* in_sizes, int n_in,
                              void* d_out, int out_size)
{
    const float* x     = (const float*)d_in[0];
    const float* tset  = (const float*)d_in[1];
    const float* tenv  = (const float*)d_in[2];
    const float* ctab  = (const float*)d_in[3];
    const float* w1    = (const float*)d_in[4];
    const float* g1    = (const float*)d_in[6];
    const float* beta1 = (const float*)d_in[7];
    const float* w2    = (const float*)d_in[8];
    const float* g2    = (const float*)d_in[10];
    const float* beta2 = (const float*)d_in[11];
    const float* w3    = (const float*)d_in[12];
    const float* b3    = (const float*)d_in[13];
    float* out = (float*)d_out;

    static bool attr_set = false;
    if (!attr_set) {
        cudaFuncSetAttribute(k3b_gemm, cudaFuncAttributeMaxDynamicSharedMemorySize, GEMM_SMEM);
        attr_set = true;
    }

    k1_feat<<<NB1, 256>>>(x, tset, tenv, ctab);
    k2_fin1<<<1, 512>>>(w1, g1, beta1);
    k2b_bsplit<<<HID * HID / 256, 256>>>(w2);
    k3a_layer1<<<B_ROWS / 16, 256>>>();
    dim3 g3(4, B_ROWS / 128);
    k3b_gemm<<<g3, GTHREADS, GEMM_SMEM>>>();
    k5_fin2<<<HID, 256>>>(g2, beta2);
    k6_out<<<4096, 256>>>(w3, b3, out);
}